// round 1
// baseline (speedup 1.0000x reference)
#include <cuda_runtime.h>
#include <math.h>

#define BB 4
#define TT 2048
#define CC 1024
#define HH 16
#define DH 64
#define MM (BB*TT)   // 8192

// Scratch (device globals: allocation-free per harness rules)
__device__ float g_Q[(size_t)MM*CC];
__device__ float g_K[(size_t)MM*CC];
__device__ float g_V[(size_t)MM*CC];
__device__ float g_Y[(size_t)MM*CC];

// ---------------------------------------------------------------------------
// GEMM: out[m,n] = sum_k A[m,k] * W[n,k] + bias[n]
// M=8192, N=1024, K=1024. 128x128 block tile, BK=8, 8x8 per thread.
// HEAD_LAYOUT=1: scatter output to [B,H,T,DH]; else row-major [M,N].
// ---------------------------------------------------------------------------
template<int HEAD_LAYOUT>
__global__ __launch_bounds__(256, 2)
void gemm_bias_kernel(const float* __restrict__ A, const float* __restrict__ W,
                      const float* __restrict__ bias, float* __restrict__ out)
{
    const int K = CC, N = CC;
    __shared__ float As[8][128];
    __shared__ float Bs[8][128];

    const int tid = threadIdx.x;
    const int m0 = blockIdx.y * 128;
    const int n0 = blockIdx.x * 128;
    const int tx = tid & 15;       // 0..15
    const int ty = tid >> 4;       // 0..15

    const int lr = tid >> 1;       // 0..127 (row of the 128-row panel)
    const int lc = (tid & 1) << 2; // 0 or 4 (k offset)

    float acc[8][8];
#pragma unroll
    for (int i = 0; i < 8; i++)
#pragma unroll
        for (int j = 0; j < 8; j++) acc[i][j] = 0.f;

    for (int k0 = 0; k0 < K; k0 += 8) {
        float4 av = *reinterpret_cast<const float4*>(&A[(size_t)(m0 + lr) * K + k0 + lc]);
        float4 bv = *reinterpret_cast<const float4*>(&W[(size_t)(n0 + lr) * K + k0 + lc]);
        As[lc + 0][lr] = av.x; As[lc + 1][lr] = av.y;
        As[lc + 2][lr] = av.z; As[lc + 3][lr] = av.w;
        Bs[lc + 0][lr] = bv.x; Bs[lc + 1][lr] = bv.y;
        Bs[lc + 2][lr] = bv.z; Bs[lc + 3][lr] = bv.w;
        __syncthreads();

#pragma unroll
        for (int kk = 0; kk < 8; kk++) {
            float a[8], b[8];
            *reinterpret_cast<float4*>(&a[0]) = *reinterpret_cast<const float4*>(&As[kk][ty * 8]);
            *reinterpret_cast<float4*>(&a[4]) = *reinterpret_cast<const float4*>(&As[kk][ty * 8 + 4]);
            *reinterpret_cast<float4*>(&b[0]) = *reinterpret_cast<const float4*>(&Bs[kk][tx * 8]);
            *reinterpret_cast<float4*>(&b[4]) = *reinterpret_cast<const float4*>(&Bs[kk][tx * 8 + 4]);
#pragma unroll
            for (int i = 0; i < 8; i++)
#pragma unroll
                for (int j = 0; j < 8; j++)
                    acc[i][j] += a[i] * b[j];
        }
        __syncthreads();
    }

#pragma unroll
    for (int i = 0; i < 8; i++) {
        const int m = m0 + ty * 8 + i;
        const int b = m / TT, t = m % TT;
#pragma unroll
        for (int j = 0; j < 8; j++) {
            const int n = n0 + tx * 8 + j;
            const float v = acc[i][j] + bias[n];
            if (HEAD_LAYOUT) {
                const int h = n >> 6;       // /DH
                const int d = n & 63;       // %DH
                out[(((size_t)(b * HH + h) * TT + t) * DH) + d] = v;
            } else {
                out[(size_t)m * N + n] = v;
            }
        }
    }
}

// ---------------------------------------------------------------------------
// Flash attention (fp32), causal. Q/K/V in [B,H,T,DH]. Output Y in [B,T,C].
// One CTA = one (b,h) x 64-row Q tile. 256 threads: 64 rows x 4 per row.
// K smem tile is XOR-swizzled so the S-loop LDS.128 reads are conflict-free.
// ---------------------------------------------------------------------------
#define PADW 68

__global__ __launch_bounds__(256, 2)
void flash_kernel(const float* __restrict__ Q, const float* __restrict__ K,
                  const float* __restrict__ V, float* __restrict__ Y)
{
    extern __shared__ float smem[];
    float (*Qs)[PADW] = (float(*)[PADW])(smem);
    float (*Ks)[PADW] = (float(*)[PADW])(smem + 64 * PADW);
    float (*Vs)[PADW] = (float(*)[PADW])(smem + 2 * 64 * PADW);
    float (*Ps)[PADW] = (float(*)[PADW])(smem + 3 * 64 * PADW);

    const int tid = threadIdx.x;
    const int row = tid >> 2;   // 0..63
    const int c   = tid & 3;    // 0..3  (column quarter)
    const int bh  = blockIdx.y; // b*H + h
    const int q0  = blockIdx.x << 6;

    const float* Qb = Q + (size_t)bh * TT * DH;
    const float* Kb = K + (size_t)bh * TT * DH;
    const float* Vb = V + (size_t)bh * TT * DH;

    // Load Q tile (64x64)
#pragma unroll
    for (int r = 0; r < 4; r++) {
        const int f  = tid + r * 256;
        const int qr = f >> 4;
        const int c4 = (f & 15) << 2;
        *reinterpret_cast<float4*>(&Qs[qr][c4]) =
            *reinterpret_cast<const float4*>(&Qb[(size_t)(q0 + qr) * DH + c4]);
    }

    float acc[16];
#pragma unroll
    for (int j = 0; j < 16; j++) acc[j] = 0.f;
    float mrun = -INFINITY, lrun = 0.f;
    const float scale = 0.125f; // 1/sqrt(64)

    __syncthreads();

    const int nkt = (q0 >> 6) + 1;
    for (int kt = 0; kt < nkt; kt++) {
        const int k0 = kt << 6;
        // Load K (swizzled) and V tiles
#pragma unroll
        for (int r = 0; r < 4; r++) {
            const int f  = tid + r * 256;
            const int rr = f >> 4;
            const int c4 = (f & 15) << 2;
            const int sw = (((c4 >> 2) ^ (rr >> 4)) << 2);  // xor-swizzle per 16-row group
            *reinterpret_cast<float4*>(&Ks[rr][sw]) =
                *reinterpret_cast<const float4*>(&Kb[(size_t)(k0 + rr) * DH + c4]);
            *reinterpret_cast<float4*>(&Vs[rr][c4]) =
                *reinterpret_cast<const float4*>(&Vb[(size_t)(k0 + rr) * DH + c4]);
        }
        __syncthreads();

        // S = scale * Q K^T  (each thread: 16 columns c*16..c*16+15 of its row)
        float s[16];
#pragma unroll
        for (int cc = 0; cc < 16; cc++) s[cc] = 0.f;
#pragma unroll
        for (int d4 = 0; d4 < 16; d4++) {
            const float4 q4 = *reinterpret_cast<const float4*>(&Qs[row][d4 << 2]);
            const int swd = ((d4 ^ c) << 2);
#pragma unroll
            for (int cc = 0; cc < 16; cc++) {
                const float4 k4 = *reinterpret_cast<const float4*>(&Ks[c * 16 + cc][swd]);
                s[cc] += q4.x * k4.x + q4.y * k4.y + q4.z * k4.z + q4.w * k4.w;
            }
        }

        const bool diag = (kt == nkt - 1);
#pragma unroll
        for (int cc = 0; cc < 16; cc++) {
            s[cc] *= scale;
            if (diag && (k0 + c * 16 + cc > q0 + row)) s[cc] = -INFINITY;
        }

        // Row max over 16 local + 4-thread group (lanes aligned to 4)
        float mx = s[0];
#pragma unroll
        for (int cc = 1; cc < 16; cc++) mx = fmaxf(mx, s[cc]);
        mx = fmaxf(mx, __shfl_xor_sync(0xffffffffu, mx, 1));
        mx = fmaxf(mx, __shfl_xor_sync(0xffffffffu, mx, 2));

        const float mnew  = fmaxf(mrun, mx);
        const float alpha = __expf(mrun - mnew);
        float lsum = 0.f;
#pragma unroll
        for (int cc = 0; cc < 16; cc++) {
            const float p = __expf(s[cc] - mnew);
            Ps[row][c * 16 + cc] = p;
            lsum += p;
        }
        lsum += __shfl_xor_sync(0xffffffffu, lsum, 1);
        lsum += __shfl_xor_sync(0xffffffffu, lsum, 2);
        lrun = lrun * alpha + lsum;
        mrun = mnew;
#pragma unroll
        for (int j = 0; j < 16; j++) acc[j] *= alpha;
        __syncthreads();

        // acc += P * V  (thread covers output dims c*16..c*16+15)
#pragma unroll
        for (int k = 0; k < 64; k++) {
            const float pk = Ps[row][k];
            const float4 v0 = *reinterpret_cast<const float4*>(&Vs[k][c * 16 + 0]);
            const float4 v1 = *reinterpret_cast<const float4*>(&Vs[k][c * 16 + 4]);
            const float4 v2 = *reinterpret_cast<const float4*>(&Vs[k][c * 16 + 8]);
            const float4 v3 = *reinterpret_cast<const float4*>(&Vs[k][c * 16 + 12]);
            acc[0]  += pk * v0.x; acc[1]  += pk * v0.y; acc[2]  += pk * v0.z; acc[3]  += pk * v0.w;
            acc[4]  += pk * v1.x; acc[5]  += pk * v1.y; acc[6]  += pk * v1.z; acc[7]  += pk * v1.w;
            acc[8]  += pk * v2.x; acc[9]  += pk * v2.y; acc[10] += pk * v2.z; acc[11] += pk * v2.w;
            acc[12] += pk * v3.x; acc[13] += pk * v3.y; acc[14] += pk * v3.z; acc[15] += pk * v3.w;
        }
        __syncthreads();
    }

    const float inv = 1.f / lrun;
    const int b = bh / HH, h = bh % HH;
    const size_t base = ((size_t)b * TT + q0 + row) * CC + h * DH + c * 16;
#pragma unroll
    for (int j = 0; j < 16; j++) Y[base + j] = acc[j] * inv;
}

// ---------------------------------------------------------------------------
extern "C" void kernel_launch(void* const* d_in, const int* in_sizes, int n_in,
                              void* d_out, int out_size)
{
    const float* x  = (const float*)d_in[0];
    const float* Wq = (const float*)d_in[1];
    const float* bq = (const float*)d_in[2];
    const float* Wk = (const float*)d_in[3];
    const float* bk = (const float*)d_in[4];
    const float* Wv = (const float*)d_in[5];
    const float* bv = (const float*)d_in[6];
    const float* Wo = (const float*)d_in[7];
    const float* bo = (const float*)d_in[8];
    float* out = (float*)d_out;

    float *Qp, *Kp, *Vp, *Yp;
    cudaGetSymbolAddress((void**)&Qp, g_Q);
    cudaGetSymbolAddress((void**)&Kp, g_K);
    cudaGetSymbolAddress((void**)&Vp, g_V);
    cudaGetSymbolAddress((void**)&Yp, g_Y);

    const int flash_smem = 4 * 64 * PADW * sizeof(float); // 69632 B
    cudaFuncSetAttribute(flash_kernel, cudaFuncAttributeMaxDynamicSharedMemorySize, flash_smem);

    dim3 gblk(256);
    dim3 ggrid(CC / 128, MM / 128);   // (8, 64)

    gemm_bias_kernel<1><<<ggrid, gblk>>>(x, Wq, bq, Qp);
    gemm_bias_kernel<1><<<ggrid, gblk>>>(x, Wk, bk, Kp);
    gemm_bias_kernel<1><<<ggrid, gblk>>>(x, Wv, bv, Vp);

    flash_kernel<<<dim3(TT / 64, BB * HH), 256, flash_smem>>>(Qp, Kp, Vp, Yp);

    gemm_bias_kernel<0><<<ggrid, gblk>>>(Yp, Wo, bo, out);
}

// round 2
// speedup vs baseline: 1.3322x; 1.3322x over previous
#include <cuda_runtime.h>
#include <math.h>

#define BB 4
#define TT 2048
#define CC 1024
#define HH 16
#define DH 64
#define MM (BB*TT)   // 8192

// Scratch (device globals: allocation-free per harness rules)
__device__ float g_Q[(size_t)MM*CC];
__device__ float g_K[(size_t)MM*CC];
__device__ float g_V[(size_t)MM*CC];
__device__ float g_Y[(size_t)MM*CC];

__device__ __forceinline__ unsigned f2tf32(float f) {
    unsigned u;
    asm("cvt.rna.tf32.f32 %0, %1;" : "=r"(u) : "f"(f));
    return u;
}

__device__ __forceinline__ void mma_tf32(float c[4], const unsigned a[4], const unsigned b[2]) {
    asm volatile(
        "mma.sync.aligned.m16n8k8.row.col.f32.tf32.tf32.f32 "
        "{%0,%1,%2,%3}, {%4,%5,%6,%7}, {%8,%9}, {%0,%1,%2,%3};"
        : "+f"(c[0]), "+f"(c[1]), "+f"(c[2]), "+f"(c[3])
        : "r"(a[0]), "r"(a[1]), "r"(a[2]), "r"(a[3]), "r"(b[0]), "r"(b[1]));
}

// ---------------------------------------------------------------------------
// tf32 tensor-core GEMM: out[m,n] = sum_k A[m,k] * W[n,k] + bias[n]
// M=8192, N=1024, K=1024. 128x128 block tile, BK=16 double-buffered.
// 8 warps, each a 64x32 warp tile of m16n8k8 frags.
// HEAD_LAYOUT=1: scatter output to [B,H,T,DH]; else row-major [M,N].
// ---------------------------------------------------------------------------
#define GPAD 20

template<int HEAD_LAYOUT>
__global__ __launch_bounds__(256, 2)
void gemm_tf32_kernel(const float* __restrict__ A, const float* __restrict__ W,
                      const float* __restrict__ bias, float* __restrict__ out)
{
    const int K = CC, N = CC;
    __shared__ unsigned As[2][128][GPAD];
    __shared__ unsigned Bs[2][128][GPAD];

    const int tid  = threadIdx.x;
    const int lane = tid & 31;
    const int warp = tid >> 5;
    const int m0 = blockIdx.y * 128;
    const int n0 = blockIdx.x * 128;
    const int wRow = (warp & 1) * 64;   // 2 warp-rows of 64
    const int wCol = (warp >> 1) * 32;  // 4 warp-cols of 32
    const int gq = lane >> 2;           // groupID 0..7
    const int gt = lane & 3;            // thread-in-group 0..3

    float acc[4][4][4];
#pragma unroll
    for (int mf = 0; mf < 4; mf++)
#pragma unroll
        for (int nf = 0; nf < 4; nf++)
#pragma unroll
            for (int r = 0; r < 4; r++) acc[mf][nf][r] = 0.f;

    // global-load mapping: 512 float4 per tile per matrix; 2 per thread
    const int r0row = tid >> 2;              // f = tid      -> rows 0..63
    const int r0kc  = (tid & 3) << 2;
    const int r1row = (tid + 256) >> 2;      // f = tid+256  -> rows 64..127
    const int r1kc  = r0kc;

    // preload kb = 0
    {
        float4 a0 = *reinterpret_cast<const float4*>(&A[(size_t)(m0 + r0row) * K + r0kc]);
        float4 a1 = *reinterpret_cast<const float4*>(&A[(size_t)(m0 + r1row) * K + r1kc]);
        float4 b0 = *reinterpret_cast<const float4*>(&W[(size_t)(n0 + r0row) * K + r0kc]);
        float4 b1 = *reinterpret_cast<const float4*>(&W[(size_t)(n0 + r1row) * K + r1kc]);
        As[0][r0row][r0kc+0]=f2tf32(a0.x); As[0][r0row][r0kc+1]=f2tf32(a0.y);
        As[0][r0row][r0kc+2]=f2tf32(a0.z); As[0][r0row][r0kc+3]=f2tf32(a0.w);
        As[0][r1row][r1kc+0]=f2tf32(a1.x); As[0][r1row][r1kc+1]=f2tf32(a1.y);
        As[0][r1row][r1kc+2]=f2tf32(a1.z); As[0][r1row][r1kc+3]=f2tf32(a1.w);
        Bs[0][r0row][r0kc+0]=f2tf32(b0.x); Bs[0][r0row][r0kc+1]=f2tf32(b0.y);
        Bs[0][r0row][r0kc+2]=f2tf32(b0.z); Bs[0][r0row][r0kc+3]=f2tf32(b0.w);
        Bs[0][r1row][r1kc+0]=f2tf32(b1.x); Bs[0][r1row][r1kc+1]=f2tf32(b1.y);
        Bs[0][r1row][r1kc+2]=f2tf32(b1.z); Bs[0][r1row][r1kc+3]=f2tf32(b1.w);
    }
    __syncthreads();

    int cur = 0;
    const int NKB = K / 16;  // 64
    for (int kb = 0; kb < NKB; kb++) {
        float4 pa0, pa1, pb0, pb1;
        const bool has_next = (kb + 1 < NKB);
        if (has_next) {
            const int kc = (kb + 1) * 16;
            pa0 = *reinterpret_cast<const float4*>(&A[(size_t)(m0 + r0row) * K + kc + r0kc]);
            pa1 = *reinterpret_cast<const float4*>(&A[(size_t)(m0 + r1row) * K + kc + r1kc]);
            pb0 = *reinterpret_cast<const float4*>(&W[(size_t)(n0 + r0row) * K + kc + r0kc]);
            pb1 = *reinterpret_cast<const float4*>(&W[(size_t)(n0 + r1row) * K + kc + r1kc]);
        }

        // compute: 2 k-steps of 8
#pragma unroll
        for (int ks = 0; ks < 16; ks += 8) {
            unsigned afr[4][4];
#pragma unroll
            for (int mf = 0; mf < 4; mf++) {
                const int rb = wRow + mf * 16 + gq;
                afr[mf][0] = As[cur][rb    ][ks + gt];
                afr[mf][1] = As[cur][rb + 8][ks + gt];
                afr[mf][2] = As[cur][rb    ][ks + 4 + gt];
                afr[mf][3] = As[cur][rb + 8][ks + 4 + gt];
            }
            unsigned bfr[4][2];
#pragma unroll
            for (int nf = 0; nf < 4; nf++) {
                const int cb = wCol + nf * 8 + gq;
                bfr[nf][0] = Bs[cur][cb][ks + gt];
                bfr[nf][1] = Bs[cur][cb][ks + 4 + gt];
            }
#pragma unroll
            for (int mf = 0; mf < 4; mf++)
#pragma unroll
                for (int nf = 0; nf < 4; nf++)
                    mma_tf32(acc[mf][nf], afr[mf], bfr[nf]);
        }

        if (has_next) {
            const int nb = cur ^ 1;
            As[nb][r0row][r0kc+0]=f2tf32(pa0.x); As[nb][r0row][r0kc+1]=f2tf32(pa0.y);
            As[nb][r0row][r0kc+2]=f2tf32(pa0.z); As[nb][r0row][r0kc+3]=f2tf32(pa0.w);
            As[nb][r1row][r1kc+0]=f2tf32(pa1.x); As[nb][r1row][r1kc+1]=f2tf32(pa1.y);
            As[nb][r1row][r1kc+2]=f2tf32(pa1.z); As[nb][r1row][r1kc+3]=f2tf32(pa1.w);
            Bs[nb][r0row][r0kc+0]=f2tf32(pb0.x); Bs[nb][r0row][r0kc+1]=f2tf32(pb0.y);
            Bs[nb][r0row][r0kc+2]=f2tf32(pb0.z); Bs[nb][r0row][r0kc+3]=f2tf32(pb0.w);
            Bs[nb][r1row][r1kc+0]=f2tf32(pb1.x); Bs[nb][r1row][r1kc+1]=f2tf32(pb1.y);
            Bs[nb][r1row][r1kc+2]=f2tf32(pb1.z); Bs[nb][r1row][r1kc+3]=f2tf32(pb1.w);
        }
        __syncthreads();
        cur ^= 1;
    }

    // epilogue
#pragma unroll
    for (int nf = 0; nf < 4; nf++) {
        const int col = n0 + wCol + nf * 8 + gt * 2;
        const float b0 = bias[col], b1 = bias[col + 1];
#pragma unroll
        for (int mf = 0; mf < 4; mf++) {
            const int row = m0 + wRow + mf * 16 + gq;
#pragma unroll
            for (int half = 0; half < 2; half++) {
                const int r = row + half * 8;
                const float v0 = acc[mf][nf][half * 2 + 0] + b0;
                const float v1 = acc[mf][nf][half * 2 + 1] + b1;
                if (HEAD_LAYOUT) {
                    const int b = r / TT, t = r % TT;
                    const int h = col >> 6, d = col & 63;
                    float2* p = reinterpret_cast<float2*>(
                        &out[(((size_t)(b * HH + h) * TT + t) * DH) + d]);
                    *p = make_float2(v0, v1);
                } else {
                    float2* p = reinterpret_cast<float2*>(&out[(size_t)r * CC + col]);
                    *p = make_float2(v0, v1);
                }
            }
        }
    }
}

// ---------------------------------------------------------------------------
// Flash attention (fp32), causal. Q/K/V in [B,H,T,DH]. Output Y in [B,T,C].
// ---------------------------------------------------------------------------
#define PADW 68

__global__ __launch_bounds__(256, 2)
void flash_kernel(const float* __restrict__ Q, const float* __restrict__ K,
                  const float* __restrict__ V, float* __restrict__ Y)
{
    extern __shared__ float smem[];
    float (*Qs)[PADW] = (float(*)[PADW])(smem);
    float (*Ks)[PADW] = (float(*)[PADW])(smem + 64 * PADW);
    float (*Vs)[PADW] = (float(*)[PADW])(smem + 2 * 64 * PADW);
    float (*Ps)[PADW] = (float(*)[PADW])(smem + 3 * 64 * PADW);

    const int tid = threadIdx.x;
    const int row = tid >> 2;
    const int c   = tid & 3;
    const int bh  = blockIdx.y;
    const int q0  = blockIdx.x << 6;

    const float* Qb = Q + (size_t)bh * TT * DH;
    const float* Kb = K + (size_t)bh * TT * DH;
    const float* Vb = V + (size_t)bh * TT * DH;

#pragma unroll
    for (int r = 0; r < 4; r++) {
        const int f  = tid + r * 256;
        const int qr = f >> 4;
        const int c4 = (f & 15) << 2;
        *reinterpret_cast<float4*>(&Qs[qr][c4]) =
            *reinterpret_cast<const float4*>(&Qb[(size_t)(q0 + qr) * DH + c4]);
    }

    float acc[16];
#pragma unroll
    for (int j = 0; j < 16; j++) acc[j] = 0.f;
    float mrun = -INFINITY, lrun = 0.f;
    const float scale = 0.125f;

    __syncthreads();

    const int nkt = (q0 >> 6) + 1;
    for (int kt = 0; kt < nkt; kt++) {
        const int k0 = kt << 6;
#pragma unroll
        for (int r = 0; r < 4; r++) {
            const int f  = tid + r * 256;
            const int rr = f >> 4;
            const int c4 = (f & 15) << 2;
            const int sw = (((c4 >> 2) ^ (rr >> 4)) << 2);
            *reinterpret_cast<float4*>(&Ks[rr][sw]) =
                *reinterpret_cast<const float4*>(&Kb[(size_t)(k0 + rr) * DH + c4]);
            *reinterpret_cast<float4*>(&Vs[rr][c4]) =
                *reinterpret_cast<const float4*>(&Vb[(size_t)(k0 + rr) * DH + c4]);
        }
        __syncthreads();

        float s[16];
#pragma unroll
        for (int cc = 0; cc < 16; cc++) s[cc] = 0.f;
#pragma unroll
        for (int d4 = 0; d4 < 16; d4++) {
            const float4 q4 = *reinterpret_cast<const float4*>(&Qs[row][d4 << 2]);
            const int swd = ((d4 ^ c) << 2);
#pragma unroll
            for (int cc = 0; cc < 16; cc++) {
                const float4 k4 = *reinterpret_cast<const float4*>(&Ks[c * 16 + cc][swd]);
                s[cc] += q4.x * k4.x + q4.y * k4.y + q4.z * k4.z + q4.w * k4.w;
            }
        }

        const bool diag = (kt == nkt - 1);
#pragma unroll
        for (int cc = 0; cc < 16; cc++) {
            s[cc] *= scale;
            if (diag && (k0 + c * 16 + cc > q0 + row)) s[cc] = -INFINITY;
        }

        float mx = s[0];
#pragma unroll
        for (int cc = 1; cc < 16; cc++) mx = fmaxf(mx, s[cc]);
        mx = fmaxf(mx, __shfl_xor_sync(0xffffffffu, mx, 1));
        mx = fmaxf(mx, __shfl_xor_sync(0xffffffffu, mx, 2));

        const float mnew  = fmaxf(mrun, mx);
        const float alpha = __expf(mrun - mnew);
        float lsum = 0.f;
#pragma unroll
        for (int cc = 0; cc < 16; cc++) {
            const float p = __expf(s[cc] - mnew);
            Ps[row][c * 16 + cc] = p;
            lsum += p;
        }
        lsum += __shfl_xor_sync(0xffffffffu, lsum, 1);
        lsum += __shfl_xor_sync(0xffffffffu, lsum, 2);
        lrun = lrun * alpha + lsum;
        mrun = mnew;
#pragma unroll
        for (int j = 0; j < 16; j++) acc[j] *= alpha;
        __syncthreads();

#pragma unroll
        for (int k = 0; k < 64; k++) {
            const float pk = Ps[row][k];
            const float4 v0 = *reinterpret_cast<const float4*>(&Vs[k][c * 16 + 0]);
            const float4 v1 = *reinterpret_cast<const float4*>(&Vs[k][c * 16 + 4]);
            const float4 v2 = *reinterpret_cast<const float4*>(&Vs[k][c * 16 + 8]);
            const float4 v3 = *reinterpret_cast<const float4*>(&Vs[k][c * 16 + 12]);
            acc[0]  += pk * v0.x; acc[1]  += pk * v0.y; acc[2]  += pk * v0.z; acc[3]  += pk * v0.w;
            acc[4]  += pk * v1.x; acc[5]  += pk * v1.y; acc[6]  += pk * v1.z; acc[7]  += pk * v1.w;
            acc[8]  += pk * v2.x; acc[9]  += pk * v2.y; acc[10] += pk * v2.z; acc[11] += pk * v2.w;
            acc[12] += pk * v3.x; acc[13] += pk * v3.y; acc[14] += pk * v3.z; acc[15] += pk * v3.w;
        }
        __syncthreads();
    }

    const float inv = 1.f / lrun;
    const int b = bh / HH, h = bh % HH;
    const size_t base = ((size_t)b * TT + q0 + row) * CC + h * DH + c * 16;
#pragma unroll
    for (int j = 0; j < 16; j++) Y[base + j] = acc[j] * inv;
}

// ---------------------------------------------------------------------------
extern "C" void kernel_launch(void* const* d_in, const int* in_sizes, int n_in,
                              void* d_out, int out_size)
{
    const float* x  = (const float*)d_in[0];
    const float* Wq = (const float*)d_in[1];
    const float* bq = (const float*)d_in[2];
    const float* Wk = (const float*)d_in[3];
    const float* bk = (const float*)d_in[4];
    const float* Wv = (const float*)d_in[5];
    const float* bv = (const float*)d_in[6];
    const float* Wo = (const float*)d_in[7];
    const float* bo = (const float*)d_in[8];
    float* out = (float*)d_out;

    float *Qp, *Kp, *Vp, *Yp;
    cudaGetSymbolAddress((void**)&Qp, g_Q);
    cudaGetSymbolAddress((void**)&Kp, g_K);
    cudaGetSymbolAddress((void**)&Vp, g_V);
    cudaGetSymbolAddress((void**)&Yp, g_Y);

    const int flash_smem = 4 * 64 * PADW * sizeof(float);
    cudaFuncSetAttribute(flash_kernel, cudaFuncAttributeMaxDynamicSharedMemorySize, flash_smem);

    dim3 gblk(256);
    dim3 ggrid(CC / 128, MM / 128);   // (8, 64)

    gemm_tf32_kernel<1><<<ggrid, gblk>>>(x, Wq, bq, Qp);
    gemm_tf32_kernel<1><<<ggrid, gblk>>>(x, Wk, bk, Kp);
    gemm_tf32_kernel<1><<<ggrid, gblk>>>(x, Wv, bv, Vp);

    flash_kernel<<<dim3(TT / 64, BB * HH), 256, flash_smem>>>(Qp, Kp, Vp, Yp);

    gemm_tf32_kernel<0><<<ggrid, gblk>>>(Yp, Wo, bo, out);
}

// round 4
// speedup vs baseline: 4.0276x; 3.0233x over previous
#include <cuda_runtime.h>
#include <math.h>
#include <stdint.h>

#define BB 4
#define TT 2048
#define CC 1024
#define HH 16
#define DH 64
#define MM (BB*TT)   // 8192

// Scratch (device globals: allocation-free per harness rules)
__device__ float g_Q[(size_t)MM*CC];
__device__ float g_K[(size_t)MM*CC];
__device__ float g_V[(size_t)MM*CC];
__device__ float g_Y[(size_t)MM*CC];

// ===========================================================================
// Helpers (base sm_103 PTX only: mma.sync / cp.async / cvt — NO tcgen05)
// ===========================================================================
__device__ __forceinline__ uint32_t smem_u32(const void* p) {
    uint32_t a;
    asm("{ .reg .u64 t; cvta.to.shared.u64 t, %1; cvt.u32.u64 %0, t; }" : "=r"(a) : "l"(p));
    return a;
}
__device__ __forceinline__ uint32_t f2tf32(float f) {
    uint32_t u;
    asm("cvt.rna.tf32.f32 %0, %1;" : "=r"(u) : "f"(f));
    return u;
}
__device__ __forceinline__ void mma8(float* c, const uint32_t* a, uint32_t b0, uint32_t b1) {
    asm volatile(
        "mma.sync.aligned.m16n8k8.row.col.f32.tf32.tf32.f32 "
        "{%0,%1,%2,%3}, {%4,%5,%6,%7}, {%8,%9}, {%0,%1,%2,%3};"
        : "+f"(c[0]), "+f"(c[1]), "+f"(c[2]), "+f"(c[3])
        : "r"(a[0]), "r"(a[1]), "r"(a[2]), "r"(a[3]), "r"(b0), "r"(b1));
}
// 3xTF32: full-precision product via hi/lo splits (drops lo*lo)
__device__ __forceinline__ void mma3(float* c, const uint32_t* ah, const uint32_t* al,
                                     uint32_t bh0, uint32_t bh1, uint32_t bl0, uint32_t bl1) {
    mma8(c, ah, bh0, bh1);
    mma8(c, ah, bl0, bl1);
    mma8(c, al, bh0, bh1);
}
__device__ __forceinline__ void cp16(uint32_t dst, const void* src) {
    asm volatile("{ .reg .u64 g; cvta.to.global.u64 g, %1; "
                 "cp.async.cg.shared.global [%0], [g], 16; }"
                 :: "r"(dst), "l"(src));
}
#define CP_COMMIT() asm volatile("cp.async.commit_group;" ::: "memory")
#define CP_WAIT2()  asm volatile("cp.async.wait_group 2;" ::: "memory")

// ===========================================================================
// GEMM: out[m,n] = sum_k A[m,k]*W[n,k] + bias[n].  M=8192,N=1024,K=1024.
// 128x128 tile, BK=16, 4-stage cp.async pipeline (raw fp32 staged, cvt->tf32
// at fragment read => rounding identical to round-2 kernel).
// 8 warps: warp tile 64x32 (4x4 m16n8k8 frags).
// ===========================================================================
#define GP 20                          // padded row width (floats)
#define STG_WORDS (128*GP)             // 2560 words / stage / matrix
#define GEMM_SMEM_BYTES (8*STG_WORDS*4)  // 4 A-stages + 4 B-stages = 81920 B

__device__ __forceinline__ void gemm_issue(
    const float* __restrict__ A, const float* __restrict__ W,
    int m0, int n0, int kb, uint32_t abase, uint32_t bbase, int r0, int c4)
{
    const float* a0 = &A[(size_t)(m0 + r0) * CC + kb * 16 + c4];
    const float* a1 = a0 + (size_t)64 * CC;
    const float* w0 = &W[(size_t)(n0 + r0) * CC + kb * 16 + c4];
    const float* w1 = w0 + (size_t)64 * CC;
    const uint32_t off = (uint32_t)(r0 * GP + c4) * 4;
    cp16(abase + off, a0);
    cp16(abase + off + 64 * GP * 4, a1);
    cp16(bbase + off, w0);
    cp16(bbase + off + 64 * GP * 4, w1);
}

template<int HEAD_LAYOUT>
__global__ __launch_bounds__(256, 2)
void gemm_tf32_pipe(const float* __restrict__ A, const float* __restrict__ W,
                    const float* __restrict__ bias, float* __restrict__ out)
{
    extern __shared__ float sm[];
    const uint32_t sbase = smem_u32(sm);

    const int tid  = threadIdx.x;
    const int lane = tid & 31;
    const int warp = tid >> 5;
    const int m0 = blockIdx.y * 128;
    const int n0 = blockIdx.x * 128;
    const int wRow = (warp & 1) * 64;
    const int wCol = (warp >> 1) * 32;
    const int gq = lane >> 2;
    const int gt = lane & 3;

    const int r0 = tid >> 2;            // 0..63
    const int c4 = (tid & 3) << 2;      // 0,4,8,12

    float acc[4][4][4];
#pragma unroll
    for (int mf = 0; mf < 4; mf++)
#pragma unroll
        for (int nf = 0; nf < 4; nf++)
#pragma unroll
            for (int r = 0; r < 4; r++) acc[mf][nf][r] = 0.f;

    // prologue: stages 0..2
#pragma unroll
    for (int s = 0; s < 3; s++) {
        gemm_issue(A, W, m0, n0, s,
                   sbase + s * STG_WORDS * 4,
                   sbase + (4 + s) * STG_WORDS * 4, r0, c4);
        CP_COMMIT();
    }

    const int NKB = CC / 16;   // 64
    for (int kb = 0; kb < NKB; kb++) {
        CP_WAIT2();
        __syncthreads();

        const int s = kb & 3;
        const float* Ab = sm + s * STG_WORDS;
        const float* Bb = sm + (4 + s) * STG_WORDS;

#pragma unroll
        for (int ks = 0; ks < 16; ks += 8) {
            uint32_t af[4][4], bf[4][2];
#pragma unroll
            for (int mf = 0; mf < 4; mf++) {
                const int rb = wRow + mf * 16 + gq;
                af[mf][0] = f2tf32(Ab[rb * GP + ks + gt]);
                af[mf][1] = f2tf32(Ab[(rb + 8) * GP + ks + gt]);
                af[mf][2] = f2tf32(Ab[rb * GP + ks + 4 + gt]);
                af[mf][3] = f2tf32(Ab[(rb + 8) * GP + ks + 4 + gt]);
            }
#pragma unroll
            for (int nf = 0; nf < 4; nf++) {
                const int cb = wCol + nf * 8 + gq;
                bf[nf][0] = f2tf32(Bb[cb * GP + ks + gt]);
                bf[nf][1] = f2tf32(Bb[cb * GP + ks + 4 + gt]);
            }
#pragma unroll
            for (int mf = 0; mf < 4; mf++)
#pragma unroll
                for (int nf = 0; nf < 4; nf++)
                    mma8(acc[mf][nf], af[mf], bf[nf][0], bf[nf][1]);
        }

        if (kb + 3 < NKB) {
            const int sn = (kb + 3) & 3;
            gemm_issue(A, W, m0, n0, kb + 3,
                       sbase + sn * STG_WORDS * 4,
                       sbase + (4 + sn) * STG_WORDS * 4, r0, c4);
        }
        CP_COMMIT();
    }

    // epilogue (round-2 proven layout)
#pragma unroll
    for (int nf = 0; nf < 4; nf++) {
        const int col = n0 + wCol + nf * 8 + gt * 2;
        const float b0 = bias[col], b1 = bias[col + 1];
#pragma unroll
        for (int mf = 0; mf < 4; mf++) {
            const int row = m0 + wRow + mf * 16 + gq;
#pragma unroll
            for (int half = 0; half < 2; half++) {
                const int r = row + half * 8;
                const float v0 = acc[mf][nf][half * 2 + 0] + b0;
                const float v1 = acc[mf][nf][half * 2 + 1] + b1;
                if (HEAD_LAYOUT) {
                    const int b = r / TT, t = r % TT;
                    const int h = col >> 6, d = col & 63;
                    *reinterpret_cast<float2*>(
                        &out[(((size_t)(b * HH + h) * TT + t) * DH) + d]) =
                        make_float2(v0, v1);
                } else {
                    *reinterpret_cast<float2*>(&out[(size_t)r * CC + col]) =
                        make_float2(v0, v1);
                }
            }
        }
    }
}

// ===========================================================================
// Flash attention, causal, 3xTF32 mma.sync. Q/K/V in [B,H,T,DH] -> Y [B,T,C].
// CTA: 128-row Q tile, 8 warps x 16 rows; K/V tiles of 64 keys.
// All operands split hi/lo (tf32) => near-fp32 accuracy.
// ===========================================================================
#define KPAD 68
#define VPAD 72
#define PPAD 68
#define KSH_OFF 0
#define KSL_OFF (64*KPAD)                    // 4352
#define VSH_OFF (KSL_OFF + 64*KPAD)          // 8704
#define VSL_OFF (VSH_OFF + 64*VPAD)          // 13312
#define PSH_OFF (VSL_OFF + 64*VPAD)          // 17920
#define PSL_OFF (PSH_OFF + 128*PPAD)         // 26624
#define FL_WORDS (PSL_OFF + 128*PPAD)        // 35328 words = 141312 B

__global__ __launch_bounds__(256, 1)
void flash_mma(const float* __restrict__ Q, const float* __restrict__ K,
               const float* __restrict__ V, float* __restrict__ Y)
{
    extern __shared__ float sm[];
    uint32_t* smu = reinterpret_cast<uint32_t*>(sm);

    const int tid  = threadIdx.x;
    const int lane = tid & 31;
    const int w    = tid >> 5;      // warp 0..7
    const int gq   = lane >> 2;     // 0..7
    const int gt   = lane & 3;      // 0..3

    const int bh = blockIdx.y;
    const int q0 = blockIdx.x << 7;   // 128-row Q tile

    const float* Qb = Q + (size_t)bh * TT * DH;
    const float* Kb = K + (size_t)bh * TT * DH;
    const float* Vb = V + (size_t)bh * TT * DH;

    const float NEG = -1e30f;

    // ---- stage Q tile into PsH region (row-major, pad 68), then frag+split ----
#pragma unroll
    for (int i = 0; i < 8; i++) {
        const int f   = tid + i * 256;
        const int row = f >> 4;
        const int cc  = (f & 15) << 2;
        *reinterpret_cast<float4*>(&sm[PSH_OFF + row * PPAD + cc]) =
            *reinterpret_cast<const float4*>(&Qb[(size_t)(q0 + row) * DH + cc]);
    }
    __syncthreads();

    uint32_t qfh[8][4], qfl[8][4];
    const int qrl = w * 16 + gq;      // local q row (frag half 0)
#pragma unroll
    for (int kd = 0; kd < 8; kd++) {
        float x0 = sm[PSH_OFF + qrl * PPAD + kd * 8 + gt];
        float x1 = sm[PSH_OFF + (qrl + 8) * PPAD + kd * 8 + gt];
        float x2 = sm[PSH_OFF + qrl * PPAD + kd * 8 + 4 + gt];
        float x3 = sm[PSH_OFF + (qrl + 8) * PPAD + kd * 8 + 4 + gt];
        qfh[kd][0] = f2tf32(x0); qfl[kd][0] = f2tf32(x0 - __uint_as_float(qfh[kd][0]));
        qfh[kd][1] = f2tf32(x1); qfl[kd][1] = f2tf32(x1 - __uint_as_float(qfh[kd][1]));
        qfh[kd][2] = f2tf32(x2); qfl[kd][2] = f2tf32(x2 - __uint_as_float(qfh[kd][2]));
        qfh[kd][3] = f2tf32(x3); qfl[kd][3] = f2tf32(x3 - __uint_as_float(qfh[kd][3]));
    }

    float acc[8][4];
#pragma unroll
    for (int nf = 0; nf < 8; nf++)
#pragma unroll
        for (int r = 0; r < 4; r++) acc[nf][r] = 0.f;
    float m0r = NEG, m1r = NEG, l0 = 0.f, l1 = 0.f;

    const int row0g = q0 + w * 16 + gq;
    const int row1g = row0g + 8;

    const int nkt = (q0 >> 6) + 2;
    for (int kt = 0; kt < nkt; kt++) {
        const int k0 = kt << 6;

        // ---- load K,V tiles, split hi/lo ----
#pragma unroll
        for (int i = 0; i < 4; i++) {
            const int f   = tid + i * 256;
            const int key = f >> 4;
            const int cc  = (f & 15) << 2;
            float4 kv = *reinterpret_cast<const float4*>(&Kb[(size_t)(k0 + key) * DH + cc]);
            float4 vv = *reinterpret_cast<const float4*>(&Vb[(size_t)(k0 + key) * DH + cc]);
            uint4 kh, kl, vh, vl;
            kh.x = f2tf32(kv.x); kl.x = f2tf32(kv.x - __uint_as_float(kh.x));
            kh.y = f2tf32(kv.y); kl.y = f2tf32(kv.y - __uint_as_float(kh.y));
            kh.z = f2tf32(kv.z); kl.z = f2tf32(kv.z - __uint_as_float(kh.z));
            kh.w = f2tf32(kv.w); kl.w = f2tf32(kv.w - __uint_as_float(kh.w));
            vh.x = f2tf32(vv.x); vl.x = f2tf32(vv.x - __uint_as_float(vh.x));
            vh.y = f2tf32(vv.y); vl.y = f2tf32(vv.y - __uint_as_float(vh.y));
            vh.z = f2tf32(vv.z); vl.z = f2tf32(vv.z - __uint_as_float(vh.z));
            vh.w = f2tf32(vv.w); vl.w = f2tf32(vv.w - __uint_as_float(vh.w));
            *reinterpret_cast<uint4*>(&smu[KSH_OFF + key * KPAD + cc]) = kh;
            *reinterpret_cast<uint4*>(&smu[KSL_OFF + key * KPAD + cc]) = kl;
            *reinterpret_cast<uint4*>(&smu[VSH_OFF + key * VPAD + cc]) = vh;
            *reinterpret_cast<uint4*>(&smu[VSL_OFF + key * VPAD + cc]) = vl;
        }
        __syncthreads();

        const bool active = (k0 <= q0 + w * 16 + 15);
        if (active) {
            // ---- S = Q K^T (3xTF32) ----
            float sc[8][4];
#pragma unroll
            for (int nf = 0; nf < 8; nf++)
#pragma unroll
                for (int r = 0; r < 4; r++) sc[nf][r] = 0.f;

#pragma unroll
            for (int kd = 0; kd < 8; kd++) {
#pragma unroll
                for (int nf = 0; nf < 8; nf++) {
                    const int rowk = (nf * 8 + gq) * KPAD + kd * 8;
                    uint32_t bh0 = smu[KSH_OFF + rowk + gt];
                    uint32_t bh1 = smu[KSH_OFF + rowk + 4 + gt];
                    uint32_t bl0 = smu[KSL_OFF + rowk + gt];
                    uint32_t bl1 = smu[KSL_OFF + rowk + 4 + gt];
                    mma3(sc[nf], qfh[kd], qfl[kd], bh0, bh1, bl0, bl1);
                }
            }

            // ---- scale + causal mask + online softmax ----
            float mx0 = NEG, mx1 = NEG;
#pragma unroll
            for (int nf = 0; nf < 8; nf++) {
                const int cb = k0 + nf * 8 + 2 * gt;
                sc[nf][0] = (cb     <= row0g) ? sc[nf][0] * 0.125f : NEG;
                sc[nf][1] = (cb + 1 <= row0g) ? sc[nf][1] * 0.125f : NEG;
                sc[nf][2] = (cb     <= row1g) ? sc[nf][2] * 0.125f : NEG;
                sc[nf][3] = (cb + 1 <= row1g) ? sc[nf][3] * 0.125f : NEG;
                mx0 = fmaxf(mx0, fmaxf(sc[nf][0], sc[nf][1]));
                mx1 = fmaxf(mx1, fmaxf(sc[nf][2], sc[nf][3]));
            }
            mx0 = fmaxf(mx0, __shfl_xor_sync(0xffffffffu, mx0, 1));
            mx0 = fmaxf(mx0, __shfl_xor_sync(0xffffffffu, mx0, 2));
            mx1 = fmaxf(mx1, __shfl_xor_sync(0xffffffffu, mx1, 1));
            mx1 = fmaxf(mx1, __shfl_xor_sync(0xffffffffu, mx1, 2));

            const float mn0 = fmaxf(m0r, mx0);
            const float mn1 = fmaxf(m1r, mx1);
            const float a0 = __expf(m0r - mn0);
            const float a1 = __expf(m1r - mn1);
            float ls0 = 0.f, ls1 = 0.f;

#pragma unroll
            for (int nf = 0; nf < 8; nf++) {
                float p0 = __expf(sc[nf][0] - mn0);
                float p1 = __expf(sc[nf][1] - mn0);
                float p2 = __expf(sc[nf][2] - mn1);
                float p3 = __expf(sc[nf][3] - mn1);
                ls0 += p0 + p1;
                ls1 += p2 + p3;
                uint32_t h0 = f2tf32(p0), h1 = f2tf32(p1);
                uint32_t h2 = f2tf32(p2), h3 = f2tf32(p3);
                uint32_t e0 = f2tf32(p0 - __uint_as_float(h0));
                uint32_t e1 = f2tf32(p1 - __uint_as_float(h1));
                uint32_t e2 = f2tf32(p2 - __uint_as_float(h2));
                uint32_t e3 = f2tf32(p3 - __uint_as_float(h3));
                const int wi0 = (w * 16 + gq) * PPAD + nf * 8 + 2 * gt;
                const int wi1 = (w * 16 + gq + 8) * PPAD + nf * 8 + 2 * gt;
                *reinterpret_cast<uint2*>(&smu[PSH_OFF + wi0]) = make_uint2(h0, h1);
                *reinterpret_cast<uint2*>(&smu[PSH_OFF + wi1]) = make_uint2(h2, h3);
                *reinterpret_cast<uint2*>(&smu[PSL_OFF + wi0]) = make_uint2(e0, e1);
                *reinterpret_cast<uint2*>(&smu[PSL_OFF + wi1]) = make_uint2(e2, e3);
            }
            ls0 += __shfl_xor_sync(0xffffffffu, ls0, 1);
            ls0 += __shfl_xor_sync(0xffffffffu, ls0, 2);
            ls1 += __shfl_xor_sync(0xffffffffu, ls1, 1);
            ls1 += __shfl_xor_sync(0xffffffffu, ls1, 2);
            m0r = mn0; m1r = mn1;
            l0 = l0 * a0 + ls0;
            l1 = l1 * a1 + ls1;
#pragma unroll
            for (int nf = 0; nf < 8; nf++) {
                acc[nf][0] *= a0; acc[nf][1] *= a0;
                acc[nf][2] *= a1; acc[nf][3] *= a1;
            }
        }
        __syncthreads();

        if (active) {
            // ---- acc += P V (3xTF32) ----
#pragma unroll
            for (int kk = 0; kk < 8; kk++) {
                uint32_t aph[4], apl[4];
                const int p0i = (w * 16 + gq) * PPAD + kk * 8;
                const int p1i = (w * 16 + gq + 8) * PPAD + kk * 8;
                aph[0] = smu[PSH_OFF + p0i + gt];
                aph[1] = smu[PSH_OFF + p1i + gt];
                aph[2] = smu[PSH_OFF + p0i + 4 + gt];
                aph[3] = smu[PSH_OFF + p1i + 4 + gt];
                apl[0] = smu[PSL_OFF + p0i + gt];
                apl[1] = smu[PSL_OFF + p1i + gt];
                apl[2] = smu[PSL_OFF + p0i + 4 + gt];
                apl[3] = smu[PSL_OFF + p1i + 4 + gt];
#pragma unroll
                for (int nf = 0; nf < 8; nf++) {
                    const int v0i = (kk * 8 + gt) * VPAD + nf * 8 + gq;
                    const int v1i = (kk * 8 + 4 + gt) * VPAD + nf * 8 + gq;
                    uint32_t bh0 = smu[VSH_OFF + v0i];
                    uint32_t bh1 = smu[VSH_OFF + v1i];
                    uint32_t bl0 = smu[VSL_OFF + v0i];
                    uint32_t bl1 = smu[VSL_OFF + v1i];
                    mma3(acc[nf], aph, apl, bh0, bh1, bl0, bl1);
                }
            }
        }
        __syncthreads();
    }

    // ---- epilogue: normalize, write Y [B,T,C] ----
    const float i0 = 1.f / l0;
    const float i1 = 1.f / l1;
    const int b = bh >> 4, h = bh & 15;
    const size_t base0 = ((size_t)b * TT + row0g) * CC + h * DH;
    const size_t base1 = ((size_t)b * TT + row1g) * CC + h * DH;
#pragma unroll
    for (int nf = 0; nf < 8; nf++) {
        const int col = nf * 8 + 2 * gt;
        *reinterpret_cast<float2*>(&Y[base0 + col]) =
            make_float2(acc[nf][0] * i0, acc[nf][1] * i0);
        *reinterpret_cast<float2*>(&Y[base1 + col]) =
            make_float2(acc[nf][2] * i1, acc[nf][3] * i1);
    }
}

// ---------------------------------------------------------------------------
extern "C" void kernel_launch(void* const* d_in, const int* in_sizes, int n_in,
                              void* d_out, int out_size)
{
    const float* x  = (const float*)d_in[0];
    const float* Wq = (const float*)d_in[1];
    const float* bq = (const float*)d_in[2];
    const float* Wk = (const float*)d_in[3];
    const float* bk = (const float*)d_in[4];
    const float* Wv = (const float*)d_in[5];
    const float* bv = (const float*)d_in[6];
    const float* Wo = (const float*)d_in[7];
    const float* bo = (const float*)d_in[8];
    float* out = (float*)d_out;

    float *Qp, *Kp, *Vp, *Yp;
    cudaGetSymbolAddress((void**)&Qp, g_Q);
    cudaGetSymbolAddress((void**)&Kp, g_K);
    cudaGetSymbolAddress((void**)&Vp, g_V);
    cudaGetSymbolAddress((void**)&Yp, g_Y);

    cudaFuncSetAttribute(gemm_tf32_pipe<1>,
                         cudaFuncAttributeMaxDynamicSharedMemorySize, GEMM_SMEM_BYTES);
    cudaFuncSetAttribute(gemm_tf32_pipe<0>,
                         cudaFuncAttributeMaxDynamicSharedMemorySize, GEMM_SMEM_BYTES);
    const int flash_smem = FL_WORDS * 4;   // 141312 B
    cudaFuncSetAttribute(flash_mma,
                         cudaFuncAttributeMaxDynamicSharedMemorySize, flash_smem);

    dim3 gblk(256);
    dim3 ggrid(CC / 128, MM / 128);   // (8, 64)

    gemm_tf32_pipe<1><<<ggrid, gblk, GEMM_SMEM_BYTES>>>(x, Wq, bq, Qp);
    gemm_tf32_pipe<1><<<ggrid, gblk, GEMM_SMEM_BYTES>>>(x, Wk, bk, Kp);
    gemm_tf32_pipe<1><<<ggrid, gblk, GEMM_SMEM_BYTES>>>(x, Wv, bv, Vp);

    flash_mma<<<dim3(TT / 128, BB * HH), 256, flash_smem>>>(Qp, Kp, Vp, Yp);

    gemm_tf32_pipe<0><<<ggrid, gblk, GEMM_SMEM_BYTES>>>(Yp, Wo, bo, out);
}

// round 5
// speedup vs baseline: 4.1678x; 1.0348x over previous
#include <cuda_runtime.h>
#include <math.h>
#include <stdint.h>

#define BB 4
#define TT 2048
#define CC 1024
#define HH 16
#define DH 64
#define MM (BB*TT)   // 8192

// Scratch (device globals: allocation-free per harness rules)
__device__ float g_Q[(size_t)MM*CC];
__device__ float g_K[(size_t)MM*CC];
__device__ float g_V[(size_t)MM*CC];
__device__ float g_Y[(size_t)MM*CC];

// ===========================================================================
// Helpers (base sm_103 PTX only: mma.sync / cp.async / cvt — NO tcgen05)
// ===========================================================================
__device__ __forceinline__ uint32_t smem_u32(const void* p) {
    uint32_t a;
    asm("{ .reg .u64 t; cvta.to.shared.u64 t, %1; cvt.u32.u64 %0, t; }" : "=r"(a) : "l"(p));
    return a;
}
__device__ __forceinline__ uint32_t f2tf32(float f) {
    uint32_t u;
    asm("cvt.rna.tf32.f32 %0, %1;" : "=r"(u) : "f"(f));
    return u;
}
__device__ __forceinline__ void mma8(float* c, const uint32_t* a, uint32_t b0, uint32_t b1) {
    asm volatile(
        "mma.sync.aligned.m16n8k8.row.col.f32.tf32.tf32.f32 "
        "{%0,%1,%2,%3}, {%4,%5,%6,%7}, {%8,%9}, {%0,%1,%2,%3};"
        : "+f"(c[0]), "+f"(c[1]), "+f"(c[2]), "+f"(c[3])
        : "r"(a[0]), "r"(a[1]), "r"(a[2]), "r"(a[3]), "r"(b0), "r"(b1));
}
// 3xTF32: full-precision product via hi/lo splits (drops lo*lo)
__device__ __forceinline__ void mma3(float* c, const uint32_t* ah, const uint32_t* al,
                                     uint32_t bh0, uint32_t bh1, uint32_t bl0, uint32_t bl1) {
    mma8(c, ah, bh0, bh1);
    mma8(c, ah, bl0, bl1);
    mma8(c, al, bh0, bh1);
}
__device__ __forceinline__ void cp16(uint32_t dst, const void* src) {
    asm volatile("{ .reg .u64 g; cvta.to.global.u64 g, %1; "
                 "cp.async.cg.shared.global [%0], [g], 16; }"
                 :: "r"(dst), "l"(src));
}
#define CP_COMMIT() asm volatile("cp.async.commit_group;" ::: "memory")
#define CP_WAIT2()  asm volatile("cp.async.wait_group 2;" ::: "memory")
#define CP_WAIT1()  asm volatile("cp.async.wait_group 1;" ::: "memory")

// ===========================================================================
// GEMM: out[m,n] = sum_k A[m,k]*W[n,k] + bias[n].  M=8192,N=1024,K=1024.
// 128x128 tile, BK=16, 4-stage cp.async pipeline.
// QKV variant does all three projections in one launch (blockIdx.z).
// ===========================================================================
#define GP 20
#define STG_WORDS (128*GP)
#define GEMM_SMEM_BYTES (8*STG_WORDS*4)  // 81920 B

__device__ __forceinline__ void gemm_issue(
    const float* __restrict__ A, const float* __restrict__ W,
    int m0, int n0, int kb, uint32_t abase, uint32_t bbase, int r0, int c4)
{
    const float* a0 = &A[(size_t)(m0 + r0) * CC + kb * 16 + c4];
    const float* a1 = a0 + (size_t)64 * CC;
    const float* w0 = &W[(size_t)(n0 + r0) * CC + kb * 16 + c4];
    const float* w1 = w0 + (size_t)64 * CC;
    const uint32_t off = (uint32_t)(r0 * GP + c4) * 4;
    cp16(abase + off, a0);
    cp16(abase + off + 64 * GP * 4, a1);
    cp16(bbase + off, w0);
    cp16(bbase + off + 64 * GP * 4, w1);
}

template<int HEAD_LAYOUT>
__device__ __forceinline__ void gemm_body(
    const float* __restrict__ A, const float* __restrict__ W,
    const float* __restrict__ bias, float* __restrict__ out)
{
    extern __shared__ float sm[];
    const uint32_t sbase = smem_u32(sm);

    const int tid  = threadIdx.x;
    const int lane = tid & 31;
    const int warp = tid >> 5;
    const int m0 = blockIdx.y * 128;
    const int n0 = blockIdx.x * 128;
    const int wRow = (warp & 1) * 64;
    const int wCol = (warp >> 1) * 32;
    const int gq = lane >> 2;
    const int gt = lane & 3;

    const int r0 = tid >> 2;
    const int c4 = (tid & 3) << 2;

    float acc[4][4][4];
#pragma unroll
    for (int mf = 0; mf < 4; mf++)
#pragma unroll
        for (int nf = 0; nf < 4; nf++)
#pragma unroll
            for (int r = 0; r < 4; r++) acc[mf][nf][r] = 0.f;

#pragma unroll
    for (int s = 0; s < 3; s++) {
        gemm_issue(A, W, m0, n0, s,
                   sbase + s * STG_WORDS * 4,
                   sbase + (4 + s) * STG_WORDS * 4, r0, c4);
        CP_COMMIT();
    }

    const int NKB = CC / 16;
    for (int kb = 0; kb < NKB; kb++) {
        CP_WAIT2();
        __syncthreads();

        const int s = kb & 3;
        const float* Ab = sm + s * STG_WORDS;
        const float* Bb = sm + (4 + s) * STG_WORDS;

#pragma unroll
        for (int ks = 0; ks < 16; ks += 8) {
            uint32_t af[4][4], bf[4][2];
#pragma unroll
            for (int mf = 0; mf < 4; mf++) {
                const int rb = wRow + mf * 16 + gq;
                af[mf][0] = f2tf32(Ab[rb * GP + ks + gt]);
                af[mf][1] = f2tf32(Ab[(rb + 8) * GP + ks + gt]);
                af[mf][2] = f2tf32(Ab[rb * GP + ks + 4 + gt]);
                af[mf][3] = f2tf32(Ab[(rb + 8) * GP + ks + 4 + gt]);
            }
#pragma unroll
            for (int nf = 0; nf < 4; nf++) {
                const int cb = wCol + nf * 8 + gq;
                bf[nf][0] = f2tf32(Bb[cb * GP + ks + gt]);
                bf[nf][1] = f2tf32(Bb[cb * GP + ks + 4 + gt]);
            }
#pragma unroll
            for (int mf = 0; mf < 4; mf++)
#pragma unroll
                for (int nf = 0; nf < 4; nf++)
                    mma8(acc[mf][nf], af[mf], bf[nf][0], bf[nf][1]);
        }

        if (kb + 3 < NKB) {
            const int sn = (kb + 3) & 3;
            gemm_issue(A, W, m0, n0, kb + 3,
                       sbase + sn * STG_WORDS * 4,
                       sbase + (4 + sn) * STG_WORDS * 4, r0, c4);
        }
        CP_COMMIT();
    }

#pragma unroll
    for (int nf = 0; nf < 4; nf++) {
        const int col = n0 + wCol + nf * 8 + gt * 2;
        const float b0 = bias[col], b1 = bias[col + 1];
#pragma unroll
        for (int mf = 0; mf < 4; mf++) {
            const int row = m0 + wRow + mf * 16 + gq;
#pragma unroll
            for (int half = 0; half < 2; half++) {
                const int r = row + half * 8;
                const float v0 = acc[mf][nf][half * 2 + 0] + b0;
                const float v1 = acc[mf][nf][half * 2 + 1] + b1;
                if (HEAD_LAYOUT) {
                    const int b = r / TT, t = r % TT;
                    const int h = col >> 6, d = col & 63;
                    *reinterpret_cast<float2*>(
                        &out[(((size_t)(b * HH + h) * TT + t) * DH) + d]) =
                        make_float2(v0, v1);
                } else {
                    *reinterpret_cast<float2*>(&out[(size_t)r * CC + col]) =
                        make_float2(v0, v1);
                }
            }
        }
    }
}

__global__ __launch_bounds__(256, 2)
void gemm_qkv(const float* __restrict__ x,
              const float* __restrict__ Wq, const float* __restrict__ bq,
              const float* __restrict__ Wk, const float* __restrict__ bk,
              const float* __restrict__ Wv, const float* __restrict__ bv,
              float* __restrict__ Qp, float* __restrict__ Kp, float* __restrict__ Vp)
{
    const float* W; const float* bias; float* out;
    if (blockIdx.z == 0)      { W = Wq; bias = bq; out = Qp; }
    else if (blockIdx.z == 1) { W = Wk; bias = bk; out = Kp; }
    else                      { W = Wv; bias = bv; out = Vp; }
    gemm_body<1>(x, W, bias, out);
}

__global__ __launch_bounds__(256, 2)
void gemm_out(const float* __restrict__ A, const float* __restrict__ W,
              const float* __restrict__ bias, float* __restrict__ out)
{
    gemm_body<0>(A, W, bias, out);
}

// ===========================================================================
// Flash attention, causal, mma.sync. Q/K/V in [B,H,T,DH] -> Y [B,T,C].
// CTA: 128-row Q tile, 8 warps x 16 rows; K/V tiles of 64 keys.
// K/V staged RAW via cp.async (double buffer), tf32 hi/lo split at frag read.
// QK^T: 3xTF32. PV: P rounded to tf32 (hi only) x V hi/lo = 2 MMAs.
// P smem is warp-private -> only __syncwarp between softmax and PV.
// ===========================================================================
#define KPAD 68
#define VPAD 72
#define PPAD 68
#define KR_OFF(b) ((b)*64*KPAD)                    // 0 / 4352
#define VR_OFF(b) (2*64*KPAD + (b)*64*VPAD)        // 8704 / 13312
#define PH_OFF    (2*64*KPAD + 2*64*VPAD)          // 17920
#define FL_WORDS  (PH_OFF + 128*PPAD)              // 26624 words = 106496 B

__device__ __forceinline__ void flash_issue(
    const float* __restrict__ Kb, const float* __restrict__ Vb,
    int k0, int buf, uint32_t sbase, int tid)
{
#pragma unroll
    for (int i = 0; i < 4; i++) {
        const int f   = tid + i * 256;
        const int row = f >> 4;
        const int cc  = (f & 15) << 2;
        cp16(sbase + (uint32_t)(KR_OFF(buf) + row * KPAD + cc) * 4,
             &Kb[(size_t)(k0 + row) * DH + cc]);
        cp16(sbase + (uint32_t)(VR_OFF(buf) + row * VPAD + cc) * 4,
             &Vb[(size_t)(k0 + row) * DH + cc]);
    }
}

__global__ __launch_bounds__(256, 1)
void flash_mma(const float* __restrict__ Q, const float* __restrict__ K,
               const float* __restrict__ V, float* __restrict__ Y)
{
    extern __shared__ float sm[];
    uint32_t* smu = reinterpret_cast<uint32_t*>(sm);
    const uint32_t sbase = smem_u32(sm);

    const int tid  = threadIdx.x;
    const int lane = tid & 31;
    const int w    = tid >> 5;
    const int gq   = lane >> 2;
    const int gt   = lane & 3;

    const int bh = blockIdx.y;
    const int q0 = blockIdx.x << 7;

    const float* Qb = Q + (size_t)bh * TT * DH;
    const float* Kb = K + (size_t)bh * TT * DH;
    const float* Vb = V + (size_t)bh * TT * DH;

    const float NEG = -1e30f;
    const int nkt = (q0 >> 6) + 2;

    // prefetch first two K/V tiles
    flash_issue(Kb, Vb, 0, 0, sbase, tid);
    CP_COMMIT();
    flash_issue(Kb, Vb, 64, 1, sbase, tid);
    CP_COMMIT();

    // ---- stage Q tile into PH region, extract hi/lo fragments ----
#pragma unroll
    for (int i = 0; i < 8; i++) {
        const int f   = tid + i * 256;
        const int row = f >> 4;
        const int cc  = (f & 15) << 2;
        *reinterpret_cast<float4*>(&sm[PH_OFF + row * PPAD + cc]) =
            *reinterpret_cast<const float4*>(&Qb[(size_t)(q0 + row) * DH + cc]);
    }
    __syncthreads();

    uint32_t qfh[8][4], qfl[8][4];
    const int qrl = w * 16 + gq;
#pragma unroll
    for (int kd = 0; kd < 8; kd++) {
        float x0 = sm[PH_OFF + qrl * PPAD + kd * 8 + gt];
        float x1 = sm[PH_OFF + (qrl + 8) * PPAD + kd * 8 + gt];
        float x2 = sm[PH_OFF + qrl * PPAD + kd * 8 + 4 + gt];
        float x3 = sm[PH_OFF + (qrl + 8) * PPAD + kd * 8 + 4 + gt];
        qfh[kd][0] = f2tf32(x0); qfl[kd][0] = f2tf32(x0 - __uint_as_float(qfh[kd][0]));
        qfh[kd][1] = f2tf32(x1); qfl[kd][1] = f2tf32(x1 - __uint_as_float(qfh[kd][1]));
        qfh[kd][2] = f2tf32(x2); qfl[kd][2] = f2tf32(x2 - __uint_as_float(qfh[kd][2]));
        qfh[kd][3] = f2tf32(x3); qfl[kd][3] = f2tf32(x3 - __uint_as_float(qfh[kd][3]));
    }
    __syncthreads();   // everyone done reading Q staging before P overwrites it

    float acc[8][4];
#pragma unroll
    for (int nf = 0; nf < 8; nf++)
#pragma unroll
        for (int r = 0; r < 4; r++) acc[nf][r] = 0.f;
    float m0r = NEG, m1r = NEG, l0 = 0.f, l1 = 0.f;

    const int row0g = q0 + w * 16 + gq;
    const int row1g = row0g + 8;

    for (int kt = 0; kt < nkt; kt++) {
        const int k0 = kt << 6;
        const int cb = kt & 1;

        CP_WAIT1();
        __syncthreads();

        const bool active = (k0 <= q0 + w * 16 + 15);
        if (active) {
            const float* Kr = sm + KR_OFF(cb);
            // ---- S = Q K^T (3xTF32), K split at read ----
            float sc[8][4];
#pragma unroll
            for (int nf = 0; nf < 8; nf++)
#pragma unroll
                for (int r = 0; r < 4; r++) sc[nf][r] = 0.f;

#pragma unroll
            for (int kd = 0; kd < 8; kd++) {
#pragma unroll
                for (int nf = 0; nf < 8; nf++) {
                    const int rowk = (nf * 8 + gq) * KPAD + kd * 8;
                    float k0f = Kr[rowk + gt];
                    float k1f = Kr[rowk + 4 + gt];
                    uint32_t bh0 = f2tf32(k0f);
                    uint32_t bl0 = f2tf32(k0f - __uint_as_float(bh0));
                    uint32_t bh1 = f2tf32(k1f);
                    uint32_t bl1 = f2tf32(k1f - __uint_as_float(bh1));
                    mma3(sc[nf], qfh[kd], qfl[kd], bh0, bh1, bl0, bl1);
                }
            }

            // ---- scale + causal mask + online softmax ----
            float mx0 = NEG, mx1 = NEG;
#pragma unroll
            for (int nf = 0; nf < 8; nf++) {
                const int c0 = k0 + nf * 8 + 2 * gt;
                sc[nf][0] = (c0     <= row0g) ? sc[nf][0] * 0.125f : NEG;
                sc[nf][1] = (c0 + 1 <= row0g) ? sc[nf][1] * 0.125f : NEG;
                sc[nf][2] = (c0     <= row1g) ? sc[nf][2] * 0.125f : NEG;
                sc[nf][3] = (c0 + 1 <= row1g) ? sc[nf][3] * 0.125f : NEG;
                mx0 = fmaxf(mx0, fmaxf(sc[nf][0], sc[nf][1]));
                mx1 = fmaxf(mx1, fmaxf(sc[nf][2], sc[nf][3]));
            }
            mx0 = fmaxf(mx0, __shfl_xor_sync(0xffffffffu, mx0, 1));
            mx0 = fmaxf(mx0, __shfl_xor_sync(0xffffffffu, mx0, 2));
            mx1 = fmaxf(mx1, __shfl_xor_sync(0xffffffffu, mx1, 1));
            mx1 = fmaxf(mx1, __shfl_xor_sync(0xffffffffu, mx1, 2));

            const float mn0 = fmaxf(m0r, mx0);
            const float mn1 = fmaxf(m1r, mx1);
            const float a0 = __expf(m0r - mn0);
            const float a1 = __expf(m1r - mn1);
            float ls0 = 0.f, ls1 = 0.f;

#pragma unroll
            for (int nf = 0; nf < 8; nf++) {
                float p0 = __expf(sc[nf][0] - mn0);
                float p1 = __expf(sc[nf][1] - mn0);
                float p2 = __expf(sc[nf][2] - mn1);
                float p3 = __expf(sc[nf][3] - mn1);
                ls0 += p0 + p1;
                ls1 += p2 + p3;
                const int wi0 = (w * 16 + gq) * PPAD + nf * 8 + 2 * gt;
                const int wi1 = (w * 16 + gq + 8) * PPAD + nf * 8 + 2 * gt;
                *reinterpret_cast<uint2*>(&smu[PH_OFF + wi0]) =
                    make_uint2(f2tf32(p0), f2tf32(p1));
                *reinterpret_cast<uint2*>(&smu[PH_OFF + wi1]) =
                    make_uint2(f2tf32(p2), f2tf32(p3));
            }
            ls0 += __shfl_xor_sync(0xffffffffu, ls0, 1);
            ls0 += __shfl_xor_sync(0xffffffffu, ls0, 2);
            ls1 += __shfl_xor_sync(0xffffffffu, ls1, 1);
            ls1 += __shfl_xor_sync(0xffffffffu, ls1, 2);
            m0r = mn0; m1r = mn1;
            l0 = l0 * a0 + ls0;
            l1 = l1 * a1 + ls1;
#pragma unroll
            for (int nf = 0; nf < 8; nf++) {
                acc[nf][0] *= a0; acc[nf][1] *= a0;
                acc[nf][2] *= a1; acc[nf][3] *= a1;
            }

            __syncwarp();   // P is warp-private: warp-level ordering suffices

            // ---- acc += P_tf32 * V (V split at read, 2 MMAs) ----
            const float* Vr = sm + VR_OFF(cb);
#pragma unroll
            for (int kk = 0; kk < 8; kk++) {
                uint32_t aph[4];
                const int p0i = (w * 16 + gq) * PPAD + kk * 8;
                const int p1i = (w * 16 + gq + 8) * PPAD + kk * 8;
                aph[0] = smu[PH_OFF + p0i + gt];
                aph[1] = smu[PH_OFF + p1i + gt];
                aph[2] = smu[PH_OFF + p0i + 4 + gt];
                aph[3] = smu[PH_OFF + p1i + 4 + gt];
#pragma unroll
                for (int nf = 0; nf < 8; nf++) {
                    const int v0i = (kk * 8 + gt) * VPAD + nf * 8 + gq;
                    const int v1i = (kk * 8 + 4 + gt) * VPAD + nf * 8 + gq;
                    float v0f = Vr[v0i];
                    float v1f = Vr[v1i];
                    uint32_t vh0 = f2tf32(v0f);
                    uint32_t vl0 = f2tf32(v0f - __uint_as_float(vh0));
                    uint32_t vh1 = f2tf32(v1f);
                    uint32_t vl1 = f2tf32(v1f - __uint_as_float(vh1));
                    mma8(acc[nf], aph, vh0, vh1);
                    mma8(acc[nf], aph, vl0, vl1);
                }
            }
        }
        __syncthreads();   // all warps done with buffer cb

        if (kt + 2 < nkt)
            flash_issue(Kb, Vb, k0 + 128, cb, sbase, tid);
        CP_COMMIT();
    }

    // ---- epilogue: normalize, write Y [B,T,C] ----
    const float i0 = 1.f / l0;
    const float i1 = 1.f / l1;
    const int b = bh >> 4, h = bh & 15;
    const size_t base0 = ((size_t)b * TT + row0g) * CC + h * DH;
    const size_t base1 = ((size_t)b * TT + row1g) * CC + h * DH;
#pragma unroll
    for (int nf = 0; nf < 8; nf++) {
        const int col = nf * 8 + 2 * gt;
        *reinterpret_cast<float2*>(&Y[base0 + col]) =
            make_float2(acc[nf][0] * i0, acc[nf][1] * i0);
        *reinterpret_cast<float2*>(&Y[base1 + col]) =
            make_float2(acc[nf][2] * i1, acc[nf][3] * i1);
    }
}

// ---------------------------------------------------------------------------
extern "C" void kernel_launch(void* const* d_in, const int* in_sizes, int n_in,
                              void* d_out, int out_size)
{
    const float* x  = (const float*)d_in[0];
    const float* Wq = (const float*)d_in[1];
    const float* bq = (const float*)d_in[2];
    const float* Wk = (const float*)d_in[3];
    const float* bk = (const float*)d_in[4];
    const float* Wv = (const float*)d_in[5];
    const float* bv = (const float*)d_in[6];
    const float* Wo = (const float*)d_in[7];
    const float* bo = (const float*)d_in[8];
    float* out = (float*)d_out;

    float *Qp, *Kp, *Vp, *Yp;
    cudaGetSymbolAddress((void**)&Qp, g_Q);
    cudaGetSymbolAddress((void**)&Kp, g_K);
    cudaGetSymbolAddress((void**)&Vp, g_V);
    cudaGetSymbolAddress((void**)&Yp, g_Y);

    cudaFuncSetAttribute(gemm_qkv,
                         cudaFuncAttributeMaxDynamicSharedMemorySize, GEMM_SMEM_BYTES);
    cudaFuncSetAttribute(gemm_out,
                         cudaFuncAttributeMaxDynamicSharedMemorySize, GEMM_SMEM_BYTES);
    const int flash_smem = FL_WORDS * 4;   // 106496 B
    cudaFuncSetAttribute(flash_mma,
                         cudaFuncAttributeMaxDynamicSharedMemorySize, flash_smem);

    dim3 gblk(256);

    gemm_qkv<<<dim3(CC / 128, MM / 128, 3), gblk, GEMM_SMEM_BYTES>>>(
        x, Wq, bq, Wk, bk, Wv, bv, Qp, Kp, Vp);

    flash_mma<<<dim3(TT / 128, BB * HH), 256, flash_smem>>>(Qp, Kp, Vp, Yp);

    gemm_out<<<dim3(CC / 128, MM / 128), gblk, GEMM_SMEM_BYTES>>>(Yp, Wo, bo, out);
}

// round 6
// speedup vs baseline: 5.7215x; 1.3728x over previous
#include <cuda_runtime.h>
#include <math.h>
#include <stdint.h>

#define BB 4
#define TT 2048
#define CC 1024
#define HH 16
#define DH 64
#define MM (BB*TT)   // 8192

// Scratch (device globals: allocation-free per harness rules)
__device__ float g_Q[(size_t)MM*CC];
__device__ float g_K[(size_t)MM*CC];
__device__ float g_V[(size_t)MM*CC];
__device__ float g_Y[(size_t)MM*CC];

// ===========================================================================
// Helpers (base sm_103 PTX only)
// ===========================================================================
__device__ __forceinline__ uint32_t smem_u32(const void* p) {
    uint32_t a;
    asm("{ .reg .u64 t; cvta.to.shared.u64 t, %1; cvt.u32.u64 %0, t; }" : "=r"(a) : "l"(p));
    return a;
}
__device__ __forceinline__ uint32_t f2tf32(float f) {
    uint32_t u;
    asm("cvt.rna.tf32.f32 %0, %1;" : "=r"(u) : "f"(f));
    return u;
}
__device__ __forceinline__ float ex2(float x) {
    float r;
    asm("ex2.approx.f32 %0, %1;" : "=f"(r) : "f"(x));
    return r;
}
__device__ __forceinline__ void mma8(float* c, const uint32_t* a, uint32_t b0, uint32_t b1) {
    asm volatile(
        "mma.sync.aligned.m16n8k8.row.col.f32.tf32.tf32.f32 "
        "{%0,%1,%2,%3}, {%4,%5,%6,%7}, {%8,%9}, {%0,%1,%2,%3};"
        : "+f"(c[0]), "+f"(c[1]), "+f"(c[2]), "+f"(c[3])
        : "r"(a[0]), "r"(a[1]), "r"(a[2]), "r"(a[3]), "r"(b0), "r"(b1));
}
__device__ __forceinline__ void cp16(uint32_t dst, const void* src) {
    asm volatile("{ .reg .u64 g; cvta.to.global.u64 g, %1; "
                 "cp.async.cg.shared.global [%0], [g], 16; }"
                 :: "r"(dst), "l"(src));
}
#define CP_COMMIT() asm volatile("cp.async.commit_group;" ::: "memory")
#define CP_WAIT2()  asm volatile("cp.async.wait_group 2;" ::: "memory")
#define CP_WAIT1()  asm volatile("cp.async.wait_group 1;" ::: "memory")

// ===========================================================================
// GEMM: out[m,n] = sum_k A[m,k]*W[n,k] + bias[n].  M=8192,N=1024,K=1024.
// 128x128 tile, BK=16, 4-stage cp.async pipeline. (unchanged from round 5)
// ===========================================================================
#define GP 20
#define STG_WORDS (128*GP)
#define GEMM_SMEM_BYTES (8*STG_WORDS*4)  // 81920 B

__device__ __forceinline__ void gemm_issue(
    const float* __restrict__ A, const float* __restrict__ W,
    int m0, int n0, int kb, uint32_t abase, uint32_t bbase, int r0, int c4)
{
    const float* a0 = &A[(size_t)(m0 + r0) * CC + kb * 16 + c4];
    const float* a1 = a0 + (size_t)64 * CC;
    const float* w0 = &W[(size_t)(n0 + r0) * CC + kb * 16 + c4];
    const float* w1 = w0 + (size_t)64 * CC;
    const uint32_t off = (uint32_t)(r0 * GP + c4) * 4;
    cp16(abase + off, a0);
    cp16(abase + off + 64 * GP * 4, a1);
    cp16(bbase + off, w0);
    cp16(bbase + off + 64 * GP * 4, w1);
}

template<int HEAD_LAYOUT>
__device__ __forceinline__ void gemm_body(
    const float* __restrict__ A, const float* __restrict__ W,
    const float* __restrict__ bias, float* __restrict__ out)
{
    extern __shared__ float sm[];
    const uint32_t sbase = smem_u32(sm);

    const int tid  = threadIdx.x;
    const int lane = tid & 31;
    const int warp = tid >> 5;
    const int m0 = blockIdx.y * 128;
    const int n0 = blockIdx.x * 128;
    const int wRow = (warp & 1) * 64;
    const int wCol = (warp >> 1) * 32;
    const int gq = lane >> 2;
    const int gt = lane & 3;

    const int r0 = tid >> 2;
    const int c4 = (tid & 3) << 2;

    float acc[4][4][4];
#pragma unroll
    for (int mf = 0; mf < 4; mf++)
#pragma unroll
        for (int nf = 0; nf < 4; nf++)
#pragma unroll
            for (int r = 0; r < 4; r++) acc[mf][nf][r] = 0.f;

#pragma unroll
    for (int s = 0; s < 3; s++) {
        gemm_issue(A, W, m0, n0, s,
                   sbase + s * STG_WORDS * 4,
                   sbase + (4 + s) * STG_WORDS * 4, r0, c4);
        CP_COMMIT();
    }

    const int NKB = CC / 16;
    for (int kb = 0; kb < NKB; kb++) {
        CP_WAIT2();
        __syncthreads();

        const int s = kb & 3;
        const float* Ab = sm + s * STG_WORDS;
        const float* Bb = sm + (4 + s) * STG_WORDS;

#pragma unroll
        for (int ks = 0; ks < 16; ks += 8) {
            uint32_t af[4][4], bf[4][2];
#pragma unroll
            for (int mf = 0; mf < 4; mf++) {
                const int rb = wRow + mf * 16 + gq;
                af[mf][0] = f2tf32(Ab[rb * GP + ks + gt]);
                af[mf][1] = f2tf32(Ab[(rb + 8) * GP + ks + gt]);
                af[mf][2] = f2tf32(Ab[rb * GP + ks + 4 + gt]);
                af[mf][3] = f2tf32(Ab[(rb + 8) * GP + ks + 4 + gt]);
            }
#pragma unroll
            for (int nf = 0; nf < 4; nf++) {
                const int cb = wCol + nf * 8 + gq;
                bf[nf][0] = f2tf32(Bb[cb * GP + ks + gt]);
                bf[nf][1] = f2tf32(Bb[cb * GP + ks + 4 + gt]);
            }
#pragma unroll
            for (int mf = 0; mf < 4; mf++)
#pragma unroll
                for (int nf = 0; nf < 4; nf++)
                    mma8(acc[mf][nf], af[mf], bf[nf][0], bf[nf][1]);
        }

        if (kb + 3 < NKB) {
            const int sn = (kb + 3) & 3;
            gemm_issue(A, W, m0, n0, kb + 3,
                       sbase + sn * STG_WORDS * 4,
                       sbase + (4 + sn) * STG_WORDS * 4, r0, c4);
        }
        CP_COMMIT();
    }

#pragma unroll
    for (int nf = 0; nf < 4; nf++) {
        const int col = n0 + wCol + nf * 8 + gt * 2;
        const float b0 = bias[col], b1 = bias[col + 1];
#pragma unroll
        for (int mf = 0; mf < 4; mf++) {
            const int row = m0 + wRow + mf * 16 + gq;
#pragma unroll
            for (int half = 0; half < 2; half++) {
                const int r = row + half * 8;
                const float v0 = acc[mf][nf][half * 2 + 0] + b0;
                const float v1 = acc[mf][nf][half * 2 + 1] + b1;
                if (HEAD_LAYOUT) {
                    const int b = r / TT, t = r % TT;
                    const int h = col >> 6, d = col & 63;
                    *reinterpret_cast<float2*>(
                        &out[(((size_t)(b * HH + h) * TT + t) * DH) + d]) =
                        make_float2(v0, v1);
                } else {
                    *reinterpret_cast<float2*>(&out[(size_t)r * CC + col]) =
                        make_float2(v0, v1);
                }
            }
        }
    }
}

__global__ __launch_bounds__(256, 2)
void gemm_qkv(const float* __restrict__ x,
              const float* __restrict__ Wq, const float* __restrict__ bq,
              const float* __restrict__ Wk, const float* __restrict__ bk,
              const float* __restrict__ Wv, const float* __restrict__ bv,
              float* __restrict__ Qp, float* __restrict__ Kp, float* __restrict__ Vp)
{
    const float* W; const float* bias; float* out;
    if (blockIdx.z == 0)      { W = Wq; bias = bq; out = Qp; }
    else if (blockIdx.z == 1) { W = Wk; bias = bk; out = Kp; }
    else                      { W = Wv; bias = bv; out = Vp; }
    gemm_body<1>(x, W, bias, out);
}

__global__ __launch_bounds__(256, 2)
void gemm_out(const float* __restrict__ A, const float* __restrict__ W,
              const float* __restrict__ bias, float* __restrict__ out)
{
    gemm_body<0>(A, W, bias, out);
}

// ===========================================================================
// Flash attention, causal, single-tf32 mma.sync, 2 CTAs/SM.
// CTA: 128-row Q tile, 8 warps x 16 rows; K/V tiles of 64 keys, cp.async x2.
// Softmax in log2 domain (scale folds log2e), ex2.approx.
// ===========================================================================
#define KPAD 68
#define VPAD 72
#define PPAD 68
#define KR_OFF(b) ((b)*64*KPAD)                    // 0 / 4352
#define VR_OFF(b) (2*64*KPAD + (b)*64*VPAD)        // 8704 / 13312
#define PH_OFF    (2*64*KPAD + 2*64*VPAD)          // 17920
#define FL_WORDS  (PH_OFF + 128*PPAD)              // 26624 words = 106496 B

__device__ __forceinline__ void flash_issue(
    const float* __restrict__ Kb, const float* __restrict__ Vb,
    int k0, int buf, uint32_t sbase, int tid)
{
#pragma unroll
    for (int i = 0; i < 4; i++) {
        const int f   = tid + i * 256;
        const int row = f >> 4;
        const int cc  = (f & 15) << 2;
        cp16(sbase + (uint32_t)(KR_OFF(buf) + row * KPAD + cc) * 4,
             &Kb[(size_t)(k0 + row) * DH + cc]);
        cp16(sbase + (uint32_t)(VR_OFF(buf) + row * VPAD + cc) * 4,
             &Vb[(size_t)(k0 + row) * DH + cc]);
    }
}

__global__ __launch_bounds__(256, 2)
void flash_mma(const float* __restrict__ Q, const float* __restrict__ K,
               const float* __restrict__ V, float* __restrict__ Y)
{
    extern __shared__ float sm[];
    uint32_t* smu = reinterpret_cast<uint32_t*>(sm);
    const uint32_t sbase = smem_u32(sm);

    const int tid  = threadIdx.x;
    const int lane = tid & 31;
    const int w    = tid >> 5;
    const int gq   = lane >> 2;
    const int gt   = lane & 3;

    const int bh = blockIdx.y;
    const int q0 = blockIdx.x << 7;

    const float* Qb = Q + (size_t)bh * TT * DH;
    const float* Kb = K + (size_t)bh * TT * DH;
    const float* Vb = V + (size_t)bh * TT * DH;

    const float NEG = -1e30f;
    // softmax in log2 domain: s' = (q.k) * 0.125 * log2(e)
    const float SC = 0.18033688011112042f;
    const int nkt = (q0 >> 6) + 2;

    // prefetch first two K/V tiles
    flash_issue(Kb, Vb, 0, 0, sbase, tid);
    CP_COMMIT();
    flash_issue(Kb, Vb, 64, 1, sbase, tid);
    CP_COMMIT();

    // ---- stage Q tile into PH region, extract tf32 fragments ----
#pragma unroll
    for (int i = 0; i < 8; i++) {
        const int f   = tid + i * 256;
        const int row = f >> 4;
        const int cc  = (f & 15) << 2;
        *reinterpret_cast<float4*>(&sm[PH_OFF + row * PPAD + cc]) =
            *reinterpret_cast<const float4*>(&Qb[(size_t)(q0 + row) * DH + cc]);
    }
    __syncthreads();

    uint32_t qf[8][4];
    const int qrl = w * 16 + gq;
#pragma unroll
    for (int kd = 0; kd < 8; kd++) {
        qf[kd][0] = f2tf32(sm[PH_OFF + qrl * PPAD + kd * 8 + gt]);
        qf[kd][1] = f2tf32(sm[PH_OFF + (qrl + 8) * PPAD + kd * 8 + gt]);
        qf[kd][2] = f2tf32(sm[PH_OFF + qrl * PPAD + kd * 8 + 4 + gt]);
        qf[kd][3] = f2tf32(sm[PH_OFF + (qrl + 8) * PPAD + kd * 8 + 4 + gt]);
    }
    __syncthreads();   // everyone done reading Q staging before P overwrites it

    float acc[8][4];
#pragma unroll
    for (int nf = 0; nf < 8; nf++)
#pragma unroll
        for (int r = 0; r < 4; r++) acc[nf][r] = 0.f;
    float m0r = NEG, m1r = NEG, l0 = 0.f, l1 = 0.f;

    const int row0g = q0 + w * 16 + gq;
    const int row1g = row0g + 8;

    for (int kt = 0; kt < nkt; kt++) {
        const int k0 = kt << 6;
        const int cb = kt & 1;

        CP_WAIT1();
        __syncthreads();

        const bool active = (k0 <= q0 + w * 16 + 15);
        if (active) {
            const float* Kr = sm + KR_OFF(cb);
            // ---- S = Q K^T (single tf32) ----
            float sc[8][4];
#pragma unroll
            for (int nf = 0; nf < 8; nf++)
#pragma unroll
                for (int r = 0; r < 4; r++) sc[nf][r] = 0.f;

#pragma unroll
            for (int kd = 0; kd < 8; kd++) {
#pragma unroll
                for (int nf = 0; nf < 8; nf++) {
                    const int rowk = (nf * 8 + gq) * KPAD + kd * 8;
                    uint32_t b0 = f2tf32(Kr[rowk + gt]);
                    uint32_t b1 = f2tf32(Kr[rowk + 4 + gt]);
                    mma8(sc[nf], qf[kd], b0, b1);
                }
            }

            // ---- scale(log2) + causal mask + online softmax ----
            float mx0 = NEG, mx1 = NEG;
#pragma unroll
            for (int nf = 0; nf < 8; nf++) {
                const int c0 = k0 + nf * 8 + 2 * gt;
                sc[nf][0] = (c0     <= row0g) ? sc[nf][0] * SC : NEG;
                sc[nf][1] = (c0 + 1 <= row0g) ? sc[nf][1] * SC : NEG;
                sc[nf][2] = (c0     <= row1g) ? sc[nf][2] * SC : NEG;
                sc[nf][3] = (c0 + 1 <= row1g) ? sc[nf][3] * SC : NEG;
                mx0 = fmaxf(mx0, fmaxf(sc[nf][0], sc[nf][1]));
                mx1 = fmaxf(mx1, fmaxf(sc[nf][2], sc[nf][3]));
            }
            mx0 = fmaxf(mx0, __shfl_xor_sync(0xffffffffu, mx0, 1));
            mx0 = fmaxf(mx0, __shfl_xor_sync(0xffffffffu, mx0, 2));
            mx1 = fmaxf(mx1, __shfl_xor_sync(0xffffffffu, mx1, 1));
            mx1 = fmaxf(mx1, __shfl_xor_sync(0xffffffffu, mx1, 2));

            const float mn0 = fmaxf(m0r, mx0);
            const float mn1 = fmaxf(m1r, mx1);
            const float a0 = ex2(m0r - mn0);
            const float a1 = ex2(m1r - mn1);
            float ls0 = 0.f, ls1 = 0.f;

#pragma unroll
            for (int nf = 0; nf < 8; nf++) {
                float p0 = ex2(sc[nf][0] - mn0);
                float p1 = ex2(sc[nf][1] - mn0);
                float p2 = ex2(sc[nf][2] - mn1);
                float p3 = ex2(sc[nf][3] - mn1);
                ls0 += p0 + p1;
                ls1 += p2 + p3;
                const int wi0 = (w * 16 + gq) * PPAD + nf * 8 + 2 * gt;
                const int wi1 = (w * 16 + gq + 8) * PPAD + nf * 8 + 2 * gt;
                *reinterpret_cast<uint2*>(&smu[PH_OFF + wi0]) =
                    make_uint2(f2tf32(p0), f2tf32(p1));
                *reinterpret_cast<uint2*>(&smu[PH_OFF + wi1]) =
                    make_uint2(f2tf32(p2), f2tf32(p3));
            }
            ls0 += __shfl_xor_sync(0xffffffffu, ls0, 1);
            ls0 += __shfl_xor_sync(0xffffffffu, ls0, 2);
            ls1 += __shfl_xor_sync(0xffffffffu, ls1, 1);
            ls1 += __shfl_xor_sync(0xffffffffu, ls1, 2);
            m0r = mn0; m1r = mn1;
            l0 = l0 * a0 + ls0;
            l1 = l1 * a1 + ls1;
#pragma unroll
            for (int nf = 0; nf < 8; nf++) {
                acc[nf][0] *= a0; acc[nf][1] *= a0;
                acc[nf][2] *= a1; acc[nf][3] *= a1;
            }

            __syncwarp();   // P is warp-private

            // ---- acc += P_tf32 * V_tf32 (single MMA) ----
            const float* Vr = sm + VR_OFF(cb);
#pragma unroll
            for (int kk = 0; kk < 8; kk++) {
                uint32_t ap[4];
                const int p0i = (w * 16 + gq) * PPAD + kk * 8;
                const int p1i = (w * 16 + gq + 8) * PPAD + kk * 8;
                ap[0] = smu[PH_OFF + p0i + gt];
                ap[1] = smu[PH_OFF + p1i + gt];
                ap[2] = smu[PH_OFF + p0i + 4 + gt];
                ap[3] = smu[PH_OFF + p1i + 4 + gt];
#pragma unroll
                for (int nf = 0; nf < 8; nf++) {
                    uint32_t v0 = f2tf32(Vr[(kk * 8 + gt) * VPAD + nf * 8 + gq]);
                    uint32_t v1 = f2tf32(Vr[(kk * 8 + 4 + gt) * VPAD + nf * 8 + gq]);
                    mma8(acc[nf], ap, v0, v1);
                }
            }
        }
        __syncthreads();   // all warps done with buffer cb

        if (kt + 2 < nkt)
            flash_issue(Kb, Vb, k0 + 128, cb, sbase, tid);
        CP_COMMIT();
    }

    // ---- epilogue: normalize, write Y [B,T,C] ----
    const float i0 = 1.f / l0;
    const float i1 = 1.f / l1;
    const int b = bh >> 4, h = bh & 15;
    const size_t base0 = ((size_t)b * TT + row0g) * CC + h * DH;
    const size_t base1 = ((size_t)b * TT + row1g) * CC + h * DH;
#pragma unroll
    for (int nf = 0; nf < 8; nf++) {
        const int col = nf * 8 + 2 * gt;
        *reinterpret_cast<float2*>(&Y[base0 + col]) =
            make_float2(acc[nf][0] * i0, acc[nf][1] * i0);
        *reinterpret_cast<float2*>(&Y[base1 + col]) =
            make_float2(acc[nf][2] * i1, acc[nf][3] * i1);
    }
}

// ---------------------------------------------------------------------------
extern "C" void kernel_launch(void* const* d_in, const int* in_sizes, int n_in,
                              void* d_out, int out_size)
{
    const float* x  = (const float*)d_in[0];
    const float* Wq = (const float*)d_in[1];
    const float* bq = (const float*)d_in[2];
    const float* Wk = (const float*)d_in[3];
    const float* bk = (const float*)d_in[4];
    const float* Wv = (const float*)d_in[5];
    const float* bv = (const float*)d_in[6];
    const float* Wo = (const float*)d_in[7];
    const float* bo = (const float*)d_in[8];
    float* out = (float*)d_out;

    float *Qp, *Kp, *Vp, *Yp;
    cudaGetSymbolAddress((void**)&Qp, g_Q);
    cudaGetSymbolAddress((void**)&Kp, g_K);
    cudaGetSymbolAddress((void**)&Vp, g_V);
    cudaGetSymbolAddress((void**)&Yp, g_Y);

    cudaFuncSetAttribute(gemm_qkv,
                         cudaFuncAttributeMaxDynamicSharedMemorySize, GEMM_SMEM_BYTES);
    cudaFuncSetAttribute(gemm_out,
                         cudaFuncAttributeMaxDynamicSharedMemorySize, GEMM_SMEM_BYTES);
    const int flash_smem = FL_WORDS * 4;   // 106496 B
    cudaFuncSetAttribute(flash_mma,
                         cudaFuncAttributeMaxDynamicSharedMemorySize, flash_smem);

    dim3 gblk(256);

    gemm_qkv<<<dim3(CC / 128, MM / 128, 3), gblk, GEMM_SMEM_BYTES>>>(
        x, Wq, bq, Wk, bk, Wv, bv, Qp, Kp, Vp);

    flash_mma<<<dim3(TT / 128, BB * HH), 256, flash_smem>>>(Qp, Kp, Vp, Yp);

    gemm_out<<<dim3(CC / 128, MM / 128), gblk, GEMM_SMEM_BYTES>>>(Yp, Wo, bo, out);
}

// round 8
// speedup vs baseline: 13.0474x; 2.2804x over previous
#include <cuda_runtime.h>
#include <cuda_fp16.h>
#include <math.h>
#include <stdint.h>

#define BB 4
#define TT 2048
#define CC 1024
#define HH 16
#define DH 64
#define MM (BB*TT)   // 8192

// Scratch (device globals: allocation-free per harness rules)
__device__ __half g_xh[(size_t)MM*CC];
__device__ __half g_Wh[(size_t)4*CC*CC];
__device__ __half g_Qh[(size_t)MM*CC];
__device__ __half g_Kh[(size_t)MM*CC];
__device__ __half g_Vh[(size_t)MM*CC];
__device__ __half g_Yh[(size_t)MM*CC];

// ===========================================================================
// Helpers (base sm_103 PTX only: mma.sync f16 / ldmatrix / cp.async)
// ===========================================================================
__device__ __forceinline__ uint32_t smem_u32(const void* p) {
    uint32_t a;
    asm("{ .reg .u64 t; cvta.to.shared.u64 t, %1; cvt.u32.u64 %0, t; }" : "=r"(a) : "l"(p));
    return a;
}
__device__ __forceinline__ float ex2(float x) {
    float r;
    asm("ex2.approx.f32 %0, %1;" : "=f"(r) : "f"(x));
    return r;
}
__device__ __forceinline__ void mma16(float* c, const uint32_t* a, uint32_t b0, uint32_t b1) {
    asm volatile(
        "mma.sync.aligned.m16n8k16.row.col.f32.f16.f16.f32 "
        "{%0,%1,%2,%3}, {%4,%5,%6,%7}, {%8,%9}, {%0,%1,%2,%3};"
        : "+f"(c[0]), "+f"(c[1]), "+f"(c[2]), "+f"(c[3])
        : "r"(a[0]), "r"(a[1]), "r"(a[2]), "r"(a[3]), "r"(b0), "r"(b1));
}
__device__ __forceinline__ void ldsm4(uint32_t* r, uint32_t addr) {
    asm volatile("ldmatrix.sync.aligned.m8n8.x4.shared.b16 {%0,%1,%2,%3}, [%4];"
                 : "=r"(r[0]), "=r"(r[1]), "=r"(r[2]), "=r"(r[3]) : "r"(addr));
}
__device__ __forceinline__ void ldsm4t(uint32_t* r, uint32_t addr) {
    asm volatile("ldmatrix.sync.aligned.m8n8.x4.trans.shared.b16 {%0,%1,%2,%3}, [%4];"
                 : "=r"(r[0]), "=r"(r[1]), "=r"(r[2]), "=r"(r[3]) : "r"(addr));
}
__device__ __forceinline__ void cp16(uint32_t dst, const void* src) {
    asm volatile("{ .reg .u64 g; cvta.to.global.u64 g, %1; "
                 "cp.async.cg.shared.global [%0], [g], 16; }"
                 :: "r"(dst), "l"(src));
}
#define CP_COMMIT() asm volatile("cp.async.commit_group;" ::: "memory")
#define CP_WAIT2()  asm volatile("cp.async.wait_group 2;" ::: "memory")
#define CP_WAIT1()  asm volatile("cp.async.wait_group 1;" ::: "memory")

// ===========================================================================
// fp32 -> fp16 conversion pre-pass: x (8M) + 4 weight matrices (4x1M).
// ===========================================================================
__global__ __launch_bounds__(256)
void cvt_kernel(const float* __restrict__ x,
                const float* __restrict__ Wq, const float* __restrict__ Wk,
                const float* __restrict__ Wv, const float* __restrict__ Wo)
{
    const size_t NX = (size_t)MM * CC;       // 8388608
    const size_t NW = (size_t)CC * CC;       // 1048576
    size_t base = ((size_t)blockIdx.x * blockDim.x + threadIdx.x) * 4;

    const float* src; __half* dst; size_t off;
    if (base < NX) { src = x; dst = g_xh; off = base; }
    else {
        size_t r = base - NX;
        int w = (int)(r / NW);
        off = r % NW;
        src = (w == 0) ? Wq : (w == 1) ? Wk : (w == 2) ? Wv : Wo;
        dst = g_Wh + (size_t)w * NW;
    }
    float4 v = *reinterpret_cast<const float4*>(&src[off]);
    __half2 h0 = __floats2half2_rn(v.x, v.y);
    __half2 h1 = __floats2half2_rn(v.z, v.w);
    *reinterpret_cast<__half2*>(&dst[off])     = h0;
    *reinterpret_cast<__half2*>(&dst[off + 2]) = h1;
}

// ===========================================================================
// fp16 GEMM: out[m,n] = sum_k A[m,k]*W[n,k] + bias[n].  M=8192,N=1024,K=1024.
// 128x128 tile, BK=32 fp16, 4-stage cp.async, ldmatrix fragments.
// 8 warps: warp tile 64x32 (4x4 m16n8k16 frags).
// OUT_MODE 1: fp16 [B,H,T,DH]; OUT_MODE 0: fp32 row-major [M,N].
// ===========================================================================
#define GPH 80                       // bytes per smem row (64 data + 16 pad)
#define GSTG_B (128*GPH)             // 10240 B per stage per matrix
#define GEMM_SMEM_BYTES (8*GSTG_B)   // 81920 B

__device__ __forceinline__ void gemm_issue_h(
    const __half* __restrict__ A, const __half* __restrict__ W,
    int m0, int n0, int kb, uint32_t abase, uint32_t bbase, int tid)
{
#pragma unroll
    for (int i = 0; i < 2; i++) {
        const int f   = tid + i * 256;     // 0..511
        const int row = f >> 2;
        const int ch  = f & 3;
        cp16(abase + (uint32_t)(row * GPH + ch * 16),
             &A[(size_t)(m0 + row) * CC + kb * 32 + ch * 8]);
        cp16(bbase + (uint32_t)(row * GPH + ch * 16),
             &W[(size_t)(n0 + row) * CC + kb * 32 + ch * 8]);
    }
}

template<int OUT_MODE>
__device__ __forceinline__ void gemm_body_h(
    const __half* __restrict__ A, const __half* __restrict__ W,
    const float* __restrict__ bias, void* __restrict__ outp)
{
    extern __shared__ char smc[];
    const uint32_t sbase = smem_u32(smc);

    const int tid  = threadIdx.x;
    const int lane = tid & 31;
    const int warp = tid >> 5;
    const int m0 = blockIdx.y * 128;
    const int n0 = blockIdx.x * 128;
    const int wRow = (warp & 1) * 64;
    const int wCol = (warp >> 1) * 32;
    const int gq = lane >> 2;
    const int gt = lane & 3;

    float acc[4][4][4];
#pragma unroll
    for (int mf = 0; mf < 4; mf++)
#pragma unroll
        for (int nf = 0; nf < 4; nf++)
#pragma unroll
            for (int r = 0; r < 4; r++) acc[mf][nf][r] = 0.f;

#pragma unroll
    for (int s = 0; s < 3; s++) {
        gemm_issue_h(A, W, m0, n0, s,
                     sbase + s * GSTG_B, sbase + (4 + s) * GSTG_B, tid);
        CP_COMMIT();
    }

    // ldmatrix lane-address components
    const int a_row = lane & 15;
    const int a_koff = (lane >> 4) * 16;
    const int b_row = (lane >> 4) * 8 + (lane & 7);
    const int b_koff = ((lane >> 3) & 1) * 16;

    const int NKB = CC / 32;   // 32
    for (int kb = 0; kb < NKB; kb++) {
        CP_WAIT2();
        __syncthreads();

        const int s = kb & 3;
        const uint32_t Ab = sbase + s * GSTG_B;
        const uint32_t Bb = sbase + (4 + s) * GSTG_B;

#pragma unroll
        for (int ks = 0; ks < 2; ks++) {
            const int kbyte = ks * 32;
            uint32_t af[4][4];
#pragma unroll
            for (int mf = 0; mf < 4; mf++)
                ldsm4(af[mf], Ab + (uint32_t)((wRow + mf * 16 + a_row) * GPH + a_koff + kbyte));
            uint32_t bf[4][2];
#pragma unroll
            for (int np = 0; np < 2; np++) {
                uint32_t t[4];
                ldsm4(t, Bb + (uint32_t)((wCol + np * 16 + b_row) * GPH + b_koff + kbyte));
                bf[np * 2][0] = t[0]; bf[np * 2][1] = t[1];
                bf[np * 2 + 1][0] = t[2]; bf[np * 2 + 1][1] = t[3];
            }
#pragma unroll
            for (int mf = 0; mf < 4; mf++)
#pragma unroll
                for (int nf = 0; nf < 4; nf++)
                    mma16(acc[mf][nf], af[mf], bf[nf][0], bf[nf][1]);
        }

        if (kb + 3 < NKB) {
            const int sn = (kb + 3) & 3;
            gemm_issue_h(A, W, m0, n0, kb + 3,
                         sbase + sn * GSTG_B, sbase + (4 + sn) * GSTG_B, tid);
        }
        CP_COMMIT();
    }

#pragma unroll
    for (int nf = 0; nf < 4; nf++) {
        const int col = n0 + wCol + nf * 8 + gt * 2;
        const float b0 = bias[col], b1 = bias[col + 1];
#pragma unroll
        for (int mf = 0; mf < 4; mf++) {
            const int row = m0 + wRow + mf * 16 + gq;
#pragma unroll
            for (int half = 0; half < 2; half++) {
                const int r = row + half * 8;
                const float v0 = acc[mf][nf][half * 2 + 0] + b0;
                const float v1 = acc[mf][nf][half * 2 + 1] + b1;
                if (OUT_MODE == 1) {
                    const int b = r / TT, t = r % TT;
                    const int h = col >> 6, d = col & 63;
                    __half* out = (__half*)outp;
                    *reinterpret_cast<__half2*>(
                        &out[(((size_t)(b * HH + h) * TT + t) * DH) + d]) =
                        __floats2half2_rn(v0, v1);
                } else {
                    float* out = (float*)outp;
                    *reinterpret_cast<float2*>(&out[(size_t)r * CC + col]) =
                        make_float2(v0, v1);
                }
            }
        }
    }
}

__global__ __launch_bounds__(256, 2)
void gemm_qkv(const float* __restrict__ bq, const float* __restrict__ bk,
              const float* __restrict__ bv)
{
    const float* bias; __half* out; const __half* W;
    if (blockIdx.z == 0)      { W = g_Wh;              bias = bq; out = g_Qh; }
    else if (blockIdx.z == 1) { W = g_Wh + (size_t)CC*CC;   bias = bk; out = g_Kh; }
    else                      { W = g_Wh + (size_t)2*CC*CC; bias = bv; out = g_Vh; }
    gemm_body_h<1>(g_xh, W, bias, out);
}

__global__ __launch_bounds__(256, 2)
void gemm_out(const float* __restrict__ bo, float* __restrict__ out)
{
    gemm_body_h<0>(g_Yh, g_Wh + (size_t)3*CC*CC, bo, out);
}

// ===========================================================================
// Flash attention, causal, fp16 mma m16n8k16, 2 CTAs/SM.
// CTA: 128-row Q tile, 8 warps x 16 rows; K/V fp16 tiles of 64 keys, cp.async.
// P fp16 in smem; V via ldmatrix.trans; softmax in log2 domain.
// ===========================================================================
#define FPH 72                        // halfs per smem row (144 B)
#define KRH(b) ((b)*64*FPH)           // halfs
#define VRH(b) (2*64*FPH + (b)*64*FPH)
#define PHH    (4*64*FPH)             // 18432 halfs
#define FL_BYTES ((PHH + 128*FPH)*2)  // 55296 B

__device__ __forceinline__ void flash_issue_h(
    const __half* __restrict__ Kb, const __half* __restrict__ Vb,
    int k0, int buf, uint32_t sbase, int tid)
{
#pragma unroll
    for (int i = 0; i < 2; i++) {
        const int f   = tid + i * 256;   // 0..511
        const int row = f >> 3;
        const int ch  = f & 7;
        cp16(sbase + (uint32_t)(KRH(buf) * 2 + row * FPH * 2 + ch * 16),
             &Kb[(size_t)(k0 + row) * DH + ch * 8]);
        cp16(sbase + (uint32_t)(VRH(buf) * 2 + row * FPH * 2 + ch * 16),
             &Vb[(size_t)(k0 + row) * DH + ch * 8]);
    }
}

__global__ __launch_bounds__(256, 2)
void flash_mma(float* __restrict__ dummy)
{
    extern __shared__ char smc[];
    __half* smh = reinterpret_cast<__half*>(smc);
    const uint32_t sbase = smem_u32(smc);

    const int tid  = threadIdx.x;
    const int lane = tid & 31;
    const int w    = tid >> 5;
    const int gq   = lane >> 2;
    const int gt   = lane & 3;

    const int bh = blockIdx.y;
    const int q0 = blockIdx.x << 7;

    const __half* Qb = g_Qh + (size_t)bh * TT * DH;
    const __half* Kb = g_Kh + (size_t)bh * TT * DH;
    const __half* Vb = g_Vh + (size_t)bh * TT * DH;

    const float NEG = -1e30f;
    const float SC = 0.18033688011112042f;   // 0.125 * log2(e)
    const int nkt = (q0 >> 6) + 2;

    flash_issue_h(Kb, Vb, 0, 0, sbase, tid);
    CP_COMMIT();
    flash_issue_h(Kb, Vb, 64, 1, sbase, tid);
    CP_COMMIT();

    // ---- stage Q tile (fp16) into P region ----
    // 128 rows x 64 halfs = 1024 uint4 chunks (8 halfs each)
#pragma unroll
    for (int i = 0; i < 4; i++) {
        const int f   = tid + i * 256;   // 0..1023
        const int row = f >> 3;          // 0..127
        const int ch  = f & 7;           // 0..7
        *reinterpret_cast<uint4*>(&smh[PHH + row * FPH + ch * 8]) =
            *reinterpret_cast<const uint4*>(&Qb[(size_t)(q0 + row) * DH + ch * 8]);
    }
    __syncthreads();

    // ldmatrix lane-address components
    const int a_row  = lane & 15;
    const int a_koff = (lane >> 4) * 16;
    const int b_row  = (lane >> 4) * 8 + (lane & 7);
    const int b_koff = ((lane >> 3) & 1) * 16;
    const int t_key  = ((lane >> 3) & 1) * 8 + (lane & 7);   // trans: key within 16
    const int t_dh   = (lane >> 4);                          // trans: dh-block select

    uint32_t qf[4][4];
#pragma unroll
    for (int kd = 0; kd < 4; kd++)
        ldsm4(qf[kd], sbase + (uint32_t)((PHH + (w * 16 + a_row) * FPH) * 2 + a_koff + kd * 32));
    __syncthreads();   // all warps done reading Q before P overwrites

    float acc[8][4];
#pragma unroll
    for (int nf = 0; nf < 8; nf++)
#pragma unroll
        for (int r = 0; r < 4; r++) acc[nf][r] = 0.f;
    float m0r = NEG, m1r = NEG, l0 = 0.f, l1 = 0.f;

    const int row0g = q0 + w * 16 + gq;
    const int row1g = row0g + 8;

    for (int kt = 0; kt < nkt; kt++) {
        const int k0 = kt << 6;
        const int cb = kt & 1;

        CP_WAIT1();
        __syncthreads();

        const bool active = (k0 <= q0 + w * 16 + 15);
        if (active) {
            // ---- S = Q K^T (fp16 m16n8k16) ----
            float sc[8][4];
#pragma unroll
            for (int nf = 0; nf < 8; nf++)
#pragma unroll
                for (int r = 0; r < 4; r++) sc[nf][r] = 0.f;

#pragma unroll
            for (int kd = 0; kd < 4; kd++) {
#pragma unroll
                for (int np = 0; np < 4; np++) {
                    uint32_t t[4];
                    ldsm4(t, sbase + (uint32_t)((KRH(cb) + (np * 16 + b_row) * FPH) * 2
                                                + b_koff + kd * 32));
                    mma16(sc[np * 2],     qf[kd], t[0], t[1]);
                    mma16(sc[np * 2 + 1], qf[kd], t[2], t[3]);
                }
            }

            // ---- scale(log2) + causal mask + online softmax ----
            float mx0 = NEG, mx1 = NEG;
#pragma unroll
            for (int nf = 0; nf < 8; nf++) {
                const int c0 = k0 + nf * 8 + 2 * gt;
                sc[nf][0] = (c0     <= row0g) ? sc[nf][0] * SC : NEG;
                sc[nf][1] = (c0 + 1 <= row0g) ? sc[nf][1] * SC : NEG;
                sc[nf][2] = (c0     <= row1g) ? sc[nf][2] * SC : NEG;
                sc[nf][3] = (c0 + 1 <= row1g) ? sc[nf][3] * SC : NEG;
                mx0 = fmaxf(mx0, fmaxf(sc[nf][0], sc[nf][1]));
                mx1 = fmaxf(mx1, fmaxf(sc[nf][2], sc[nf][3]));
            }
            mx0 = fmaxf(mx0, __shfl_xor_sync(0xffffffffu, mx0, 1));
            mx0 = fmaxf(mx0, __shfl_xor_sync(0xffffffffu, mx0, 2));
            mx1 = fmaxf(mx1, __shfl_xor_sync(0xffffffffu, mx1, 1));
            mx1 = fmaxf(mx1, __shfl_xor_sync(0xffffffffu, mx1, 2));

            const float mn0 = fmaxf(m0r, mx0);
            const float mn1 = fmaxf(m1r, mx1);
            const float a0 = ex2(m0r - mn0);
            const float a1 = ex2(m1r - mn1);
            float ls0 = 0.f, ls1 = 0.f;

#pragma unroll
            for (int nf = 0; nf < 8; nf++) {
                float p0 = ex2(sc[nf][0] - mn0);
                float p1 = ex2(sc[nf][1] - mn0);
                float p2 = ex2(sc[nf][2] - mn1);
                float p3 = ex2(sc[nf][3] - mn1);
                ls0 += p0 + p1;
                ls1 += p2 + p3;
                const int col = nf * 8 + 2 * gt;
                *reinterpret_cast<__half2*>(&smh[PHH + (w * 16 + gq) * FPH + col]) =
                    __floats2half2_rn(p0, p1);
                *reinterpret_cast<__half2*>(&smh[PHH + (w * 16 + gq + 8) * FPH + col]) =
                    __floats2half2_rn(p2, p3);
            }
            ls0 += __shfl_xor_sync(0xffffffffu, ls0, 1);
            ls0 += __shfl_xor_sync(0xffffffffu, ls0, 2);
            ls1 += __shfl_xor_sync(0xffffffffu, ls1, 1);
            ls1 += __shfl_xor_sync(0xffffffffu, ls1, 2);
            m0r = mn0; m1r = mn1;
            l0 = l0 * a0 + ls0;
            l1 = l1 * a1 + ls1;
#pragma unroll
            for (int nf = 0; nf < 8; nf++) {
                acc[nf][0] *= a0; acc[nf][1] *= a0;
                acc[nf][2] *= a1; acc[nf][3] *= a1;
            }

            __syncwarp();   // P is warp-private

            // ---- acc += P * V (P via ldmatrix, V via ldmatrix.trans) ----
#pragma unroll
            for (int kk = 0; kk < 4; kk++) {
                uint32_t ap[4];
                ldsm4(ap, sbase + (uint32_t)((PHH + (w * 16 + a_row) * FPH) * 2
                                             + a_koff + kk * 32));
#pragma unroll
                for (int np = 0; np < 4; np++) {
                    uint32_t t[4];
                    const int key = kk * 16 + t_key;
                    const int dhb = (np * 2 + t_dh) * 16;    // bytes into dh
                    ldsm4t(t, sbase + (uint32_t)((VRH(cb) + key * FPH) * 2 + dhb));
                    mma16(acc[np * 2],     ap, t[0], t[1]);
                    mma16(acc[np * 2 + 1], ap, t[2], t[3]);
                }
            }
        }
        __syncthreads();   // all warps done with buffer cb

        if (kt + 2 < nkt)
            flash_issue_h(Kb, Vb, k0 + 128, cb, sbase, tid);
        CP_COMMIT();
    }

    // ---- epilogue: normalize, write Yh fp16 [B,T,C] ----
    const float i0 = 1.f / l0;
    const float i1 = 1.f / l1;
    const int b = bh >> 4, h = bh & 15;
    const size_t base0 = ((size_t)b * TT + row0g) * CC + h * DH;
    const size_t base1 = ((size_t)b * TT + row1g) * CC + h * DH;
#pragma unroll
    for (int nf = 0; nf < 8; nf++) {
        const int col = nf * 8 + 2 * gt;
        *reinterpret_cast<__half2*>(&g_Yh[base0 + col]) =
            __floats2half2_rn(acc[nf][0] * i0, acc[nf][1] * i0);
        *reinterpret_cast<__half2*>(&g_Yh[base1 + col]) =
            __floats2half2_rn(acc[nf][2] * i1, acc[nf][3] * i1);
    }
}

// ---------------------------------------------------------------------------
extern "C" void kernel_launch(void* const* d_in, const int* in_sizes, int n_in,
                              void* d_out, int out_size)
{
    const float* x  = (const float*)d_in[0];
    const float* Wq = (const float*)d_in[1];
    const float* bq = (const float*)d_in[2];
    const float* Wk = (const float*)d_in[3];
    const float* bk = (const float*)d_in[4];
    const float* Wv = (const float*)d_in[5];
    const float* bv = (const float*)d_in[6];
    const float* Wo = (const float*)d_in[7];
    const float* bo = (const float*)d_in[8];
    float* out = (float*)d_out;

    cudaFuncSetAttribute(gemm_qkv,
                         cudaFuncAttributeMaxDynamicSharedMemorySize, GEMM_SMEM_BYTES);
    cudaFuncSetAttribute(gemm_out,
                         cudaFuncAttributeMaxDynamicSharedMemorySize, GEMM_SMEM_BYTES);
    cudaFuncSetAttribute(flash_mma,
                         cudaFuncAttributeMaxDynamicSharedMemorySize, FL_BYTES);

    // fp32 -> fp16 pre-pass: 12.58M elems, 4 per thread
    const size_t NCV = ((size_t)MM * CC + (size_t)4 * CC * CC) / 4;
    cvt_kernel<<<(unsigned)(NCV / 256), 256>>>(x, Wq, Wk, Wv, Wo);

    gemm_qkv<<<dim3(CC / 128, MM / 128, 3), 256, GEMM_SMEM_BYTES>>>(bq, bk, bv);

    flash_mma<<<dim3(TT / 128, BB * HH), 256, FL_BYTES>>>(out);

    gemm_out<<<dim3(CC / 128, MM / 128), 256, GEMM_SMEM_BYTES>>>(bo, out);
}

// round 9
// speedup vs baseline: 13.6975x; 1.0498x over previous
#include <cuda_runtime.h>
#include <cuda_fp16.h>
#include <math.h>
#include <stdint.h>

#define BB 4
#define TT 2048
#define CC 1024
#define HH 16
#define DH 64
#define MM (BB*TT)   // 8192

// Scratch (device globals: allocation-free per harness rules)
__device__ __half g_xh[(size_t)MM*CC];
__device__ __half g_Wh[(size_t)4*CC*CC];
__device__ __half g_Qh[(size_t)MM*CC];
__device__ __half g_Kh[(size_t)MM*CC];
__device__ __half g_Vh[(size_t)MM*CC];
__device__ __half g_Yh[(size_t)MM*CC];

// ===========================================================================
// Helpers (base sm_103 PTX only: mma.sync f16 / ldmatrix / cp.async)
// ===========================================================================
__device__ __forceinline__ uint32_t smem_u32(const void* p) {
    uint32_t a;
    asm("{ .reg .u64 t; cvta.to.shared.u64 t, %1; cvt.u32.u64 %0, t; }" : "=r"(a) : "l"(p));
    return a;
}
__device__ __forceinline__ float ex2(float x) {
    float r;
    asm("ex2.approx.f32 %0, %1;" : "=f"(r) : "f"(x));
    return r;
}
__device__ __forceinline__ void mma16(float* c, const uint32_t* a, uint32_t b0, uint32_t b1) {
    asm volatile(
        "mma.sync.aligned.m16n8k16.row.col.f32.f16.f16.f32 "
        "{%0,%1,%2,%3}, {%4,%5,%6,%7}, {%8,%9}, {%0,%1,%2,%3};"
        : "+f"(c[0]), "+f"(c[1]), "+f"(c[2]), "+f"(c[3])
        : "r"(a[0]), "r"(a[1]), "r"(a[2]), "r"(a[3]), "r"(b0), "r"(b1));
}
__device__ __forceinline__ void ldsm4(uint32_t* r, uint32_t addr) {
    asm volatile("ldmatrix.sync.aligned.m8n8.x4.shared.b16 {%0,%1,%2,%3}, [%4];"
                 : "=r"(r[0]), "=r"(r[1]), "=r"(r[2]), "=r"(r[3]) : "r"(addr));
}
__device__ __forceinline__ void ldsm4t(uint32_t* r, uint32_t addr) {
    asm volatile("ldmatrix.sync.aligned.m8n8.x4.trans.shared.b16 {%0,%1,%2,%3}, [%4];"
                 : "=r"(r[0]), "=r"(r[1]), "=r"(r[2]), "=r"(r[3]) : "r"(addr));
}
__device__ __forceinline__ void cp16(uint32_t dst, const void* src) {
    asm volatile("{ .reg .u64 g; cvta.to.global.u64 g, %1; "
                 "cp.async.cg.shared.global [%0], [g], 16; }"
                 :: "r"(dst), "l"(src));
}
#define CP_COMMIT() asm volatile("cp.async.commit_group;" ::: "memory")
#define CP_WAIT2()  asm volatile("cp.async.wait_group 2;" ::: "memory")
#define CP_WAIT1()  asm volatile("cp.async.wait_group 1;" ::: "memory")

// ===========================================================================
// fp32 -> fp16 conversion pre-pass: x (8M) + 4 weight matrices (4x1M).
// ===========================================================================
__global__ __launch_bounds__(256)
void cvt_kernel(const float* __restrict__ x,
                const float* __restrict__ Wq, const float* __restrict__ Wk,
                const float* __restrict__ Wv, const float* __restrict__ Wo)
{
    const size_t NX = (size_t)MM * CC;       // 8388608
    const size_t NW = (size_t)CC * CC;       // 1048576
    size_t base = ((size_t)blockIdx.x * blockDim.x + threadIdx.x) * 4;

    const float* src; __half* dst; size_t off;
    if (base < NX) { src = x; dst = g_xh; off = base; }
    else {
        size_t r = base - NX;
        int w = (int)(r / NW);
        off = r % NW;
        src = (w == 0) ? Wq : (w == 1) ? Wk : (w == 2) ? Wv : Wo;
        dst = g_Wh + (size_t)w * NW;
    }
    float4 v = *reinterpret_cast<const float4*>(&src[off]);
    __half2 h0 = __floats2half2_rn(v.x, v.y);
    __half2 h1 = __floats2half2_rn(v.z, v.w);
    *reinterpret_cast<__half2*>(&dst[off])     = h0;
    *reinterpret_cast<__half2*>(&dst[off + 2]) = h1;
}

// ===========================================================================
// fp16 GEMM: out[m,n] = sum_k A[m,k]*W[n,k] + bias[n].  M=8192,N=1024,K=1024.
// 128x128 CTA tile, 4 warps (128 thr), warp tile 64x64 (4x8 m16n8k16 frags).
// BK=32, 4-stage cp.async, ldmatrix fragments.
// OUT_MODE 1: fp16 [B,H,T,DH]; OUT_MODE 0: fp32 row-major [M,N].
// ===========================================================================
#define GPH 80                       // bytes per smem row (64 data + 16 pad)
#define GSTG_B (128*GPH)             // 10240 B per stage per matrix
#define GEMM_SMEM_BYTES (8*GSTG_B)   // 81920 B

__device__ __forceinline__ void gemm_issue_h(
    const __half* __restrict__ A, const __half* __restrict__ W,
    int m0, int n0, int kb, uint32_t abase, uint32_t bbase, int tid)
{
#pragma unroll
    for (int i = 0; i < 4; i++) {
        const int f   = tid + i * 128;     // 0..511
        const int row = f >> 2;
        const int ch  = f & 3;
        cp16(abase + (uint32_t)(row * GPH + ch * 16),
             &A[(size_t)(m0 + row) * CC + kb * 32 + ch * 8]);
        cp16(bbase + (uint32_t)(row * GPH + ch * 16),
             &W[(size_t)(n0 + row) * CC + kb * 32 + ch * 8]);
    }
}

template<int OUT_MODE>
__device__ __forceinline__ void gemm_body_h(
    const __half* __restrict__ A, const __half* __restrict__ W,
    const float* __restrict__ bias, void* __restrict__ outp)
{
    extern __shared__ char smc[];
    const uint32_t sbase = smem_u32(smc);

    const int tid  = threadIdx.x;
    const int lane = tid & 31;
    const int warp = tid >> 5;          // 0..3
    const int m0 = blockIdx.y * 128;
    const int n0 = blockIdx.x * 128;
    const int wRow = (warp & 1) * 64;   // 2 warp-rows of 64
    const int wCol = (warp >> 1) * 64;  // 2 warp-cols of 64
    const int gq = lane >> 2;
    const int gt = lane & 3;

    float acc[4][8][4];
#pragma unroll
    for (int mf = 0; mf < 4; mf++)
#pragma unroll
        for (int nf = 0; nf < 8; nf++)
#pragma unroll
            for (int r = 0; r < 4; r++) acc[mf][nf][r] = 0.f;

#pragma unroll
    for (int s = 0; s < 3; s++) {
        gemm_issue_h(A, W, m0, n0, s,
                     sbase + s * GSTG_B, sbase + (4 + s) * GSTG_B, tid);
        CP_COMMIT();
    }

    // ldmatrix lane-address components
    const int a_row = lane & 15;
    const int a_koff = (lane >> 4) * 16;
    const int b_row = (lane >> 4) * 8 + (lane & 7);
    const int b_koff = ((lane >> 3) & 1) * 16;

    const int NKB = CC / 32;   // 32
    for (int kb = 0; kb < NKB; kb++) {
        CP_WAIT2();
        __syncthreads();

        const int s = kb & 3;
        const uint32_t Ab = sbase + s * GSTG_B;
        const uint32_t Bb = sbase + (4 + s) * GSTG_B;

#pragma unroll
        for (int ks = 0; ks < 2; ks++) {
            const int kbyte = ks * 32;
            uint32_t af[4][4];
#pragma unroll
            for (int mf = 0; mf < 4; mf++)
                ldsm4(af[mf], Ab + (uint32_t)((wRow + mf * 16 + a_row) * GPH + a_koff + kbyte));
            uint32_t bf[8][2];
#pragma unroll
            for (int np = 0; np < 4; np++) {
                uint32_t t[4];
                ldsm4(t, Bb + (uint32_t)((wCol + np * 16 + b_row) * GPH + b_koff + kbyte));
                bf[np * 2][0] = t[0]; bf[np * 2][1] = t[1];
                bf[np * 2 + 1][0] = t[2]; bf[np * 2 + 1][1] = t[3];
            }
#pragma unroll
            for (int mf = 0; mf < 4; mf++)
#pragma unroll
                for (int nf = 0; nf < 8; nf++)
                    mma16(acc[mf][nf], af[mf], bf[nf][0], bf[nf][1]);
        }

        if (kb + 3 < NKB) {
            const int sn = (kb + 3) & 3;
            gemm_issue_h(A, W, m0, n0, kb + 3,
                         sbase + sn * GSTG_B, sbase + (4 + sn) * GSTG_B, tid);
        }
        CP_COMMIT();
    }

#pragma unroll
    for (int nf = 0; nf < 8; nf++) {
        const int col = n0 + wCol + nf * 8 + gt * 2;
        const float b0 = bias[col], b1 = bias[col + 1];
#pragma unroll
        for (int mf = 0; mf < 4; mf++) {
            const int row = m0 + wRow + mf * 16 + gq;
#pragma unroll
            for (int half = 0; half < 2; half++) {
                const int r = row + half * 8;
                const float v0 = acc[mf][nf][half * 2 + 0] + b0;
                const float v1 = acc[mf][nf][half * 2 + 1] + b1;
                if (OUT_MODE == 1) {
                    const int b = r / TT, t = r % TT;
                    const int h = col >> 6, d = col & 63;
                    __half* out = (__half*)outp;
                    *reinterpret_cast<__half2*>(
                        &out[(((size_t)(b * HH + h) * TT + t) * DH) + d]) =
                        __floats2half2_rn(v0, v1);
                } else {
                    float* out = (float*)outp;
                    *reinterpret_cast<float2*>(&out[(size_t)r * CC + col]) =
                        make_float2(v0, v1);
                }
            }
        }
    }
}

__global__ __launch_bounds__(128, 2)
void gemm_qkv(const float* __restrict__ bq, const float* __restrict__ bk,
              const float* __restrict__ bv)
{
    const float* bias; __half* out; const __half* W;
    if (blockIdx.z == 0)      { W = g_Wh;              bias = bq; out = g_Qh; }
    else if (blockIdx.z == 1) { W = g_Wh + (size_t)CC*CC;   bias = bk; out = g_Kh; }
    else                      { W = g_Wh + (size_t)2*CC*CC; bias = bv; out = g_Vh; }
    gemm_body_h<1>(g_xh, W, bias, out);
}

__global__ __launch_bounds__(128, 2)
void gemm_out(const float* __restrict__ bo, float* __restrict__ out)
{
    gemm_body_h<0>(g_Yh, g_Wh + (size_t)3*CC*CC, bo, out);
}

// ===========================================================================
// Flash attention, causal, fp16 mma m16n8k16, 2 CTAs/SM. (unchanged round 8)
// ===========================================================================
#define FPH 72                        // halfs per smem row (144 B)
#define KRH(b) ((b)*64*FPH)
#define VRH(b) (2*64*FPH + (b)*64*FPH)
#define PHH    (4*64*FPH)
#define FL_BYTES ((PHH + 128*FPH)*2)  // 55296 B

__device__ __forceinline__ void flash_issue_h(
    const __half* __restrict__ Kb, const __half* __restrict__ Vb,
    int k0, int buf, uint32_t sbase, int tid)
{
#pragma unroll
    for (int i = 0; i < 2; i++) {
        const int f   = tid + i * 256;
        const int row = f >> 3;
        const int ch  = f & 7;
        cp16(sbase + (uint32_t)(KRH(buf) * 2 + row * FPH * 2 + ch * 16),
             &Kb[(size_t)(k0 + row) * DH + ch * 8]);
        cp16(sbase + (uint32_t)(VRH(buf) * 2 + row * FPH * 2 + ch * 16),
             &Vb[(size_t)(k0 + row) * DH + ch * 8]);
    }
}

__global__ __launch_bounds__(256, 2)
void flash_mma(float* __restrict__ dummy)
{
    extern __shared__ char smc[];
    __half* smh = reinterpret_cast<__half*>(smc);
    const uint32_t sbase = smem_u32(smc);

    const int tid  = threadIdx.x;
    const int lane = tid & 31;
    const int w    = tid >> 5;
    const int gq   = lane >> 2;
    const int gt   = lane & 3;

    const int bh = blockIdx.y;
    const int q0 = blockIdx.x << 7;

    const __half* Qb = g_Qh + (size_t)bh * TT * DH;
    const __half* Kb = g_Kh + (size_t)bh * TT * DH;
    const __half* Vb = g_Vh + (size_t)bh * TT * DH;

    const float NEG = -1e30f;
    const float SC = 0.18033688011112042f;   // 0.125 * log2(e)
    const int nkt = (q0 >> 6) + 2;

    flash_issue_h(Kb, Vb, 0, 0, sbase, tid);
    CP_COMMIT();
    flash_issue_h(Kb, Vb, 64, 1, sbase, tid);
    CP_COMMIT();

    // ---- stage Q tile (fp16) into P region ----
#pragma unroll
    for (int i = 0; i < 4; i++) {
        const int f   = tid + i * 256;
        const int row = f >> 3;
        const int ch  = f & 7;
        *reinterpret_cast<uint4*>(&smh[PHH + row * FPH + ch * 8]) =
            *reinterpret_cast<const uint4*>(&Qb[(size_t)(q0 + row) * DH + ch * 8]);
    }
    __syncthreads();

    const int a_row  = lane & 15;
    const int a_koff = (lane >> 4) * 16;
    const int b_row  = (lane >> 4) * 8 + (lane & 7);
    const int b_koff = ((lane >> 3) & 1) * 16;
    const int t_key  = ((lane >> 3) & 1) * 8 + (lane & 7);
    const int t_dh   = (lane >> 4);

    uint32_t qf[4][4];
#pragma unroll
    for (int kd = 0; kd < 4; kd++)
        ldsm4(qf[kd], sbase + (uint32_t)((PHH + (w * 16 + a_row) * FPH) * 2 + a_koff + kd * 32));
    __syncthreads();

    float acc[8][4];
#pragma unroll
    for (int nf = 0; nf < 8; nf++)
#pragma unroll
        for (int r = 0; r < 4; r++) acc[nf][r] = 0.f;
    float m0r = NEG, m1r = NEG, l0 = 0.f, l1 = 0.f;

    const int row0g = q0 + w * 16 + gq;
    const int row1g = row0g + 8;

    for (int kt = 0; kt < nkt; kt++) {
        const int k0 = kt << 6;
        const int cb = kt & 1;

        CP_WAIT1();
        __syncthreads();

        const bool active = (k0 <= q0 + w * 16 + 15);
        if (active) {
            float sc[8][4];
#pragma unroll
            for (int nf = 0; nf < 8; nf++)
#pragma unroll
                for (int r = 0; r < 4; r++) sc[nf][r] = 0.f;

#pragma unroll
            for (int kd = 0; kd < 4; kd++) {
#pragma unroll
                for (int np = 0; np < 4; np++) {
                    uint32_t t[4];
                    ldsm4(t, sbase + (uint32_t)((KRH(cb) + (np * 16 + b_row) * FPH) * 2
                                                + b_koff + kd * 32));
                    mma16(sc[np * 2],     qf[kd], t[0], t[1]);
                    mma16(sc[np * 2 + 1], qf[kd], t[2], t[3]);
                }
            }

            float mx0 = NEG, mx1 = NEG;
#pragma unroll
            for (int nf = 0; nf < 8; nf++) {
                const int c0 = k0 + nf * 8 + 2 * gt;
                sc[nf][0] = (c0     <= row0g) ? sc[nf][0] * SC : NEG;
                sc[nf][1] = (c0 + 1 <= row0g) ? sc[nf][1] * SC : NEG;
                sc[nf][2] = (c0     <= row1g) ? sc[nf][2] * SC : NEG;
                sc[nf][3] = (c0 + 1 <= row1g) ? sc[nf][3] * SC : NEG;
                mx0 = fmaxf(mx0, fmaxf(sc[nf][0], sc[nf][1]));
                mx1 = fmaxf(mx1, fmaxf(sc[nf][2], sc[nf][3]));
            }
            mx0 = fmaxf(mx0, __shfl_xor_sync(0xffffffffu, mx0, 1));
            mx0 = fmaxf(mx0, __shfl_xor_sync(0xffffffffu, mx0, 2));
            mx1 = fmaxf(mx1, __shfl_xor_sync(0xffffffffu, mx1, 1));
            mx1 = fmaxf(mx1, __shfl_xor_sync(0xffffffffu, mx1, 2));

            const float mn0 = fmaxf(m0r, mx0);
            const float mn1 = fmaxf(m1r, mx1);
            const float a0 = ex2(m0r - mn0);
            const float a1 = ex2(m1r - mn1);
            float ls0 = 0.f, ls1 = 0.f;

#pragma unroll
            for (int nf = 0; nf < 8; nf++) {
                float p0 = ex2(sc[nf][0] - mn0);
                float p1 = ex2(sc[nf][1] - mn0);
                float p2 = ex2(sc[nf][2] - mn1);
                float p3 = ex2(sc[nf][3] - mn1);
                ls0 += p0 + p1;
                ls1 += p2 + p3;
                const int col = nf * 8 + 2 * gt;
                *reinterpret_cast<__half2*>(&smh[PHH + (w * 16 + gq) * FPH + col]) =
                    __floats2half2_rn(p0, p1);
                *reinterpret_cast<__half2*>(&smh[PHH + (w * 16 + gq + 8) * FPH + col]) =
                    __floats2half2_rn(p2, p3);
            }
            ls0 += __shfl_xor_sync(0xffffffffu, ls0, 1);
            ls0 += __shfl_xor_sync(0xffffffffu, ls0, 2);
            ls1 += __shfl_xor_sync(0xffffffffu, ls1, 1);
            ls1 += __shfl_xor_sync(0xffffffffu, ls1, 2);
            m0r = mn0; m1r = mn1;
            l0 = l0 * a0 + ls0;
            l1 = l1 * a1 + ls1;
#pragma unroll
            for (int nf = 0; nf < 8; nf++) {
                acc[nf][0] *= a0; acc[nf][1] *= a0;
                acc[nf][2] *= a1; acc[nf][3] *= a1;
            }

            __syncwarp();

#pragma unroll
            for (int kk = 0; kk < 4; kk++) {
                uint32_t ap[4];
                ldsm4(ap, sbase + (uint32_t)((PHH + (w * 16 + a_row) * FPH) * 2
                                             + a_koff + kk * 32));
#pragma unroll
                for (int np = 0; np < 4; np++) {
                    uint32_t t[4];
                    const int key = kk * 16 + t_key;
                    const int dhb = (np * 2 + t_dh) * 16;
                    ldsm4t(t, sbase + (uint32_t)((VRH(cb) + key * FPH) * 2 + dhb));
                    mma16(acc[np * 2],     ap, t[0], t[1]);
                    mma16(acc[np * 2 + 1], ap, t[2], t[3]);
                }
            }
        }
        __syncthreads();

        if (kt + 2 < nkt)
            flash_issue_h(Kb, Vb, k0 + 128, cb, sbase, tid);
        CP_COMMIT();
    }

    const float i0 = 1.f / l0;
    const float i1 = 1.f / l1;
    const int b = bh >> 4, h = bh & 15;
    const size_t base0 = ((size_t)b * TT + row0g) * CC + h * DH;
    const size_t base1 = ((size_t)b * TT + row1g) * CC + h * DH;
#pragma unroll
    for (int nf = 0; nf < 8; nf++) {
        const int col = nf * 8 + 2 * gt;
        *reinterpret_cast<__half2*>(&g_Yh[base0 + col]) =
            __floats2half2_rn(acc[nf][0] * i0, acc[nf][1] * i0);
        *reinterpret_cast<__half2*>(&g_Yh[base1 + col]) =
            __floats2half2_rn(acc[nf][2] * i1, acc[nf][3] * i1);
    }
}

// ---------------------------------------------------------------------------
extern "C" void kernel_launch(void* const* d_in, const int* in_sizes, int n_in,
                              void* d_out, int out_size)
{
    const float* x  = (const float*)d_in[0];
    const float* Wq = (const float*)d_in[1];
    const float* bq = (const float*)d_in[2];
    const float* Wk = (const float*)d_in[3];
    const float* bk = (const float*)d_in[4];
    const float* Wv = (const float*)d_in[5];
    const float* bv = (const float*)d_in[6];
    const float* Wo = (const float*)d_in[7];
    const float* bo = (const float*)d_in[8];
    float* out = (float*)d_out;

    cudaFuncSetAttribute(gemm_qkv,
                         cudaFuncAttributeMaxDynamicSharedMemorySize, GEMM_SMEM_BYTES);
    cudaFuncSetAttribute(gemm_out,
                         cudaFuncAttributeMaxDynamicSharedMemorySize, GEMM_SMEM_BYTES);
    cudaFuncSetAttribute(flash_mma,
                         cudaFuncAttributeMaxDynamicSharedMemorySize, FL_BYTES);

    const size_t NCV = ((size_t)MM * CC + (size_t)4 * CC * CC) / 4;
    cvt_kernel<<<(unsigned)(NCV / 256), 256>>>(x, Wq, Wk, Wv, Wo);

    gemm_qkv<<<dim3(CC / 128, MM / 128, 3), 128, GEMM_SMEM_BYTES>>>(bq, bk, bv);

    flash_mma<<<dim3(TT / 128, BB * HH), 256, FL_BYTES>>>(out);

    gemm_out<<<dim3(CC / 128, MM / 128), 128, GEMM_SMEM_BYTES>>>(bo, out);
}